// round 3
// baseline (speedup 1.0000x reference)
#include <cuda_runtime.h>

#define SSIM_C1 1e-4f
#define SSIM_C2 9e-4f

// tile geometry
#define TW 64            // output tile width
#define TH 16            // output tile height
#define HW 74            // halo tile width  (TW + 10)
#define HH 26            // halo tile height (TH + 10)
#define SSTR 76          // vbuf row stride in floats (16B-aligned rows)
#define SP2  76          // s12 row stride in float2 units
#define NPAIR 37         // column pairs covering 74 halo columns
#define NITEM (NPAIR*8)  // 2-row chunks: 8 chunks x 37 pairs = 296
#define NBLOCKS (16*16*64)

typedef unsigned long long u64;

__device__ __align__(16) float g_partial[NBLOCKS];
__device__ int g_count = 0;

__device__ __forceinline__ u64 pack2(float lo, float hi) {
    u64 r;
    asm("mov.b64 %0, {%1,%2};" : "=l"(r) : "f"(lo), "f"(hi));
    return r;
}
__device__ __forceinline__ void unpack2(u64 v, float& lo, float& hi) {
    asm("mov.b64 {%0,%1}, %2;" : "=f"(lo), "=f"(hi) : "l"(v));
}
__device__ __forceinline__ u64 fma2(u64 a, u64 b, u64 c) {
    u64 d;
    asm("fma.rn.f32x2 %0, %1, %2, %3;" : "=l"(d) : "l"(a), "l"(b), "l"(c));
    return d;
}
__device__ __forceinline__ u64 mul2(u64 a, u64 b) {
    u64 d;
    asm("mul.rn.f32x2 %0, %1, %2;" : "=l"(d) : "l"(a), "l"(b));
    return d;
}

__global__ __launch_bounds__(256) void ssim_main(
    const float* __restrict__ img1,
    const float* __restrict__ img2,
    const float* __restrict__ kw,
    float* __restrict__ out)
{
    __shared__ __align__(16) float2 s12[HH * SP2];        // interleaved (x, y)
    __shared__ __align__(16) float vbuf[5 * TH * SSTR];   // 5 vertical-conv planes
    __shared__ float s_w[11];
    __shared__ float warpSums[8];
    __shared__ int s_isLast;

    const int tid = threadIdx.x;
    const int bx = blockIdx.x, by = blockIdx.y, bz = blockIdx.z;
    const int row0 = by * TH;
    const int col0 = bx * TW;

    // Recover 1D gaussian from 2D kernel: g[i] = row-sum (since sum(g)=1)
    if (tid < 11) {
        float s = 0.f;
        #pragma unroll
        for (int j = 0; j < 11; j++) s += kw[tid * 11 + j];
        s_w[tid] = s;
    }

    // ---- load halo tile, interleaved (zero padding outside image) ----
    const float* base1 = img1 + (size_t)bz * 1048576u;
    const float* base2 = img2 + (size_t)bz * 1048576u;
    for (int i = tid; i < HH * HW; i += 256) {
        int rr = i / HW;
        int cc = i - rr * HW;
        int gr = row0 - 5 + rr;
        int gc = col0 - 5 + cc;
        bool ok = ((unsigned)gr < 1024u) && ((unsigned)gc < 1024u);
        int gi = gr * 1024 + gc;
        float a = ok ? base1[gi] : 0.f;
        float b = ok ? base2[gi] : 0.f;
        s12[rr * SP2 + cc] = make_float2(a, b);
    }
    __syncthreads();

    // packed weights (both lanes identical)
    u64 w2[11];
    #pragma unroll
    for (int i = 0; i < 11; i++) w2[i] = pack2(s_w[i], s_w[i]);

    // ---- vertical pass: 2 output rows per item, 296 items over 256 threads ----
    for (int t = tid; t < NITEM; t += 256) {
        int c = t / NPAIR;              // chunk 0..7 -> output rows 2c, 2c+1
        int p = t - c * NPAIR;          // column pair
        u64 a00=0,a01=0,a02=0,a03=0,a04=0;
        u64 a10=0,a11=0,a12=0,a13=0,a14=0;

        const float2* sp = &s12[(2 * c) * SP2 + 2 * p];
        #pragma unroll
        for (int k = 0; k < 12; k++) {
            float4 v = *(const float4*)(sp + k * SP2);
            u64 xa = pack2(v.x, v.z);
            u64 yb = pack2(v.y, v.w);
            u64 xx = mul2(xa, xa);
            u64 yy = mul2(yb, yb);
            u64 xy = mul2(xa, yb);
            if (k <= 10) {
                u64 w = w2[k];
                a00 = fma2(w, xa, a00);
                a01 = fma2(w, yb, a01);
                a02 = fma2(w, xx, a02);
                a03 = fma2(w, yy, a03);
                a04 = fma2(w, xy, a04);
            }
            if (k >= 1) {
                u64 w = w2[k - 1];
                a10 = fma2(w, xa, a10);
                a11 = fma2(w, yb, a11);
                a12 = fma2(w, xx, a12);
                a13 = fma2(w, yy, a13);
                a14 = fma2(w, xy, a14);
            }
        }
        int off0 = (2 * c) * SSTR + 2 * p;
        int off1 = off0 + SSTR;
        *(u64*)&vbuf[0 * TH * SSTR + off0] = a00;
        *(u64*)&vbuf[1 * TH * SSTR + off0] = a01;
        *(u64*)&vbuf[2 * TH * SSTR + off0] = a02;
        *(u64*)&vbuf[3 * TH * SSTR + off0] = a03;
        *(u64*)&vbuf[4 * TH * SSTR + off0] = a04;
        *(u64*)&vbuf[0 * TH * SSTR + off1] = a10;
        *(u64*)&vbuf[1 * TH * SSTR + off1] = a11;
        *(u64*)&vbuf[2 * TH * SSTR + off1] = a12;
        *(u64*)&vbuf[3 * TH * SSTR + off1] = a13;
        *(u64*)&vbuf[4 * TH * SSTR + off1] = a14;
    }
    __syncthreads();

    // ---- horizontal pass + SSIM: each thread does 4 consecutive columns of one row ----
    const int hr  = tid >> 4;          // 0..15
    const int cl0 = (tid & 15) * 4;    // 0..60

    u64 res[5][2];
    #pragma unroll
    for (int q = 0; q < 5; q++) {
        const float* vp = &vbuf[q * TH * SSTR + hr * SSTR + cl0];
        float tv[14];
        float4 v0 = *(const float4*)(vp + 0);
        float4 v1 = *(const float4*)(vp + 4);
        float4 v2 = *(const float4*)(vp + 8);
        float2 v3 = *(const float2*)(vp + 12);
        tv[0]=v0.x; tv[1]=v0.y; tv[2]=v0.z; tv[3]=v0.w;
        tv[4]=v1.x; tv[5]=v1.y; tv[6]=v1.z; tv[7]=v1.w;
        tv[8]=v2.x; tv[9]=v2.y; tv[10]=v2.z; tv[11]=v2.w;
        tv[12]=v3.x; tv[13]=v3.y;
        u64 pk[13];
        #pragma unroll
        for (int j = 0; j < 13; j++) pk[j] = pack2(tv[j], tv[j + 1]);
        u64 a0 = 0, a1 = 0;
        #pragma unroll
        for (int j = 0; j < 11; j++) {
            a0 = fma2(w2[j], pk[j],     a0);
            a1 = fma2(w2[j], pk[j + 2], a1);
        }
        res[q][0] = a0;
        res[q][1] = a1;
    }

    float m1[4], m2[4], exx[4], eyy[4], exy[4];
    unpack2(res[0][0], m1[0], m1[1]);   unpack2(res[0][1], m1[2], m1[3]);
    unpack2(res[1][0], m2[0], m2[1]);   unpack2(res[1][1], m2[2], m2[3]);
    unpack2(res[2][0], exx[0], exx[1]); unpack2(res[2][1], exx[2], exx[3]);
    unpack2(res[3][0], eyy[0], eyy[1]); unpack2(res[3][1], eyy[2], eyy[3]);
    unpack2(res[4][0], exy[0], exy[1]); unpack2(res[4][1], exy[2], exy[3]);

    float ssum = 0.f;
    #pragma unroll
    for (int k = 0; k < 4; k++) {
        float a = m1[k], b = m2[k];
        float a2v = a * a, b2v = b * b, ab = a * b;
        float sx2 = exx[k] - a2v;
        float sy2 = eyy[k] - b2v;
        float sxy = exy[k] - ab;
        float num = (2.f * ab  + SSIM_C1) * (2.f * sxy + SSIM_C2);
        float den = (a2v + b2v + SSIM_C1) * (sx2 + sy2 + SSIM_C2);
        ssum += __fdividef(num, den);
    }

    // ---- block reduction (deterministic, no float atomics) ----
    #pragma unroll
    for (int o = 16; o > 0; o >>= 1)
        ssum += __shfl_down_sync(0xffffffffu, ssum, o);
    const int wid = tid >> 5, lane = tid & 31;
    if (lane == 0) warpSums[wid] = ssum;
    __syncthreads();
    if (tid == 0) {
        float tot = 0.f;
        #pragma unroll
        for (int i = 0; i < 8; i++) tot += warpSums[i];
        int bid = bx + 16 * (by + 64 * bz);
        g_partial[bid] = tot;
        __threadfence();
        int prev = atomicAdd(&g_count, 1);
        s_isLast = (prev == NBLOCKS - 1);
    }
    __syncthreads();

    // ---- last block folds the global mean (canonical threadfence-reduction) ----
    if (s_isLast) {
        __shared__ double dsum[8];
        const float4* p4 = (const float4*)g_partial;   // 4096 float4
        double s = 0.0;
        #pragma unroll
        for (int i = 0; i < 16; i++) {
            float4 v = p4[tid + i * 256];
            s += (double)v.x + (double)v.y + (double)v.z + (double)v.w;
        }
        #pragma unroll
        for (int o = 16; o > 0; o >>= 1)
            s += __shfl_down_sync(0xffffffffu, s, o);
        if (lane == 0) dsum[wid] = s;
        __syncthreads();
        if (tid == 0) {
            double t = 0.0;
            #pragma unroll
            for (int i = 0; i < 8; i++) t += dsum[i];
            out[0] = (float)(t / 16777216.0);
            g_count = 0;   // reset for next graph replay
        }
    }
}

extern "C" void kernel_launch(void* const* d_in, const int* in_sizes, int n_in,
                              void* d_out, int out_size)
{
    const float* img1 = (const float*)d_in[0];
    const float* img2 = (const float*)d_in[1];
    const float* kw   = (const float*)d_in[2];
    float* out = (float*)d_out;

    dim3 grid(16, 64, 16);   // 1024/64 x-tiles, 1024/16 y-tiles, 16 batch
    ssim_main<<<grid, 256>>>(img1, img2, kw, out);
}

// round 4
// speedup vs baseline: 1.1394x; 1.1394x over previous
#include <cuda_runtime.h>

#define SSIM_C1 1e-4f
#define SSIM_C2 9e-4f

// tile geometry
#define TW 64            // output tile width
#define TH 16            // output tile height
#define HW 74            // halo tile width  (TW + 10)
#define HH 26            // halo tile height (TH + 10)
#define SSTR 76          // smem row stride in floats (8B-aligned pairs, 16B rows)
#define NPAIR 37         // column pairs covering 74 halo columns
#define NITEM (NPAIR*TH) // 592 vertical items (1 output row x 1 col-pair each)
#define NBLOCKS (16*16*64)

typedef unsigned long long u64;

__device__ __align__(16) float g_partial[NBLOCKS];
__device__ int g_count = 0;

__device__ __forceinline__ u64 fma2(u64 a, u64 b, u64 c) {
    u64 d;
    asm("fma.rn.f32x2 %0, %1, %2, %3;" : "=l"(d) : "l"(a), "l"(b), "l"(c));
    return d;
}
__device__ __forceinline__ u64 mul2(u64 a, u64 b) {
    u64 d;
    asm("mul.rn.f32x2 %0, %1, %2;" : "=l"(d) : "l"(a), "l"(b));
    return d;
}
__device__ __forceinline__ u64 pack2(float lo, float hi) {
    u64 r;
    asm("mov.b64 %0, {%1,%2};" : "=l"(r) : "f"(lo), "f"(hi));
    return r;
}

__global__ __launch_bounds__(256) void ssim_main(
    const float* __restrict__ img1,
    const float* __restrict__ img2,
    const float* __restrict__ kw,
    float* __restrict__ out)
{
    __shared__ __align__(16) float s1[HH * SSTR];         // img1 halo (SoA)
    __shared__ __align__(16) float s2[HH * SSTR];         // img2 halo (SoA)
    __shared__ __align__(16) float vbuf[5 * TH * SSTR];   // 5 vertical-conv planes
    __shared__ float s_w[11];
    __shared__ float warpSums[8];
    __shared__ int s_isLast;

    const int tid = threadIdx.x;
    const int bx = blockIdx.x, by = blockIdx.y, bz = blockIdx.z;
    const int row0 = by * TH;
    const int col0 = bx * TW;

    // Recover 1D gaussian from 2D kernel: g[i] = row-sum (since sum(g)=1)
    if (tid < 11) {
        float s = 0.f;
        #pragma unroll
        for (int j = 0; j < 11; j++) s += kw[tid * 11 + j];
        s_w[tid] = s;
    }

    // ---- load halo tiles, SoA (zero padding outside image) ----
    const float* base1 = img1 + (size_t)bz * 1048576u;
    const float* base2 = img2 + (size_t)bz * 1048576u;
    for (int i = tid; i < HH * HW; i += 256) {
        int rr = i / HW;
        int cc = i - rr * HW;
        int gr = row0 - 5 + rr;
        int gc = col0 - 5 + cc;
        bool ok = ((unsigned)gr < 1024u) && ((unsigned)gc < 1024u);
        int gi = gr * 1024 + gc;
        float a = ok ? base1[gi] : 0.f;
        float b = ok ? base2[gi] : 0.f;
        s1[rr * SSTR + cc] = a;
        s2[rr * SSTR + cc] = b;
    }
    __syncthreads();

    // packed weights (both lanes identical) — built once, 11 u64
    u64 w2[11];
    #pragma unroll
    for (int i = 0; i < 11; i++) {
        float w = s_w[i];
        w2[i] = pack2(w, w);
    }

    // ---- vertical pass: 1 output row x 1 col-pair per item, direct LDS.64 ----
    for (int t = tid; t < NITEM; t += 256) {
        int r = t / NPAIR;
        int p = t - r * NPAIR;
        u64 a0 = 0, a1 = 0, a2 = 0, a3 = 0, a4 = 0;
        const u64* s1p = (const u64*)&s1[r * SSTR + 2 * p];
        const u64* s2p = (const u64*)&s2[r * SSTR + 2 * p];
        #pragma unroll
        for (int i = 0; i < 11; i++) {
            u64 xa = s1p[i * (SSTR / 2)];   // LDS.64 -> operand directly, no movs
            u64 yb = s2p[i * (SSTR / 2)];
            u64 w  = w2[i];
            a0 = fma2(w, xa, a0);
            a1 = fma2(w, yb, a1);
            a2 = fma2(w, mul2(xa, xa), a2);
            a3 = fma2(w, mul2(yb, yb), a3);
            a4 = fma2(w, mul2(xa, yb), a4);
        }
        int off = r * SSTR + 2 * p;
        *(u64*)&vbuf[0 * TH * SSTR + off] = a0;
        *(u64*)&vbuf[1 * TH * SSTR + off] = a1;
        *(u64*)&vbuf[2 * TH * SSTR + off] = a2;
        *(u64*)&vbuf[3 * TH * SSTR + off] = a3;
        *(u64*)&vbuf[4 * TH * SSTR + off] = a4;
    }
    __syncthreads();

    // ---- horizontal pass + SSIM: scalar FFMA, 4 consecutive columns per thread ----
    const int hr  = tid >> 4;          // 0..15
    const int cl0 = (tid & 15) * 4;    // 0..60

    float res[5][4];
    #pragma unroll
    for (int q = 0; q < 5; q++) {
        const float* vp = &vbuf[q * TH * SSTR + hr * SSTR + cl0];
        float tv[14];
        float4 v0 = *(const float4*)(vp + 0);
        float4 v1 = *(const float4*)(vp + 4);
        float4 v2 = *(const float4*)(vp + 8);
        float2 v3 = *(const float2*)(vp + 12);
        tv[0]=v0.x; tv[1]=v0.y; tv[2]=v0.z; tv[3]=v0.w;
        tv[4]=v1.x; tv[5]=v1.y; tv[6]=v1.z; tv[7]=v1.w;
        tv[8]=v2.x; tv[9]=v2.y; tv[10]=v2.z; tv[11]=v2.w;
        tv[12]=v3.x; tv[13]=v3.y;
        float o0 = 0.f, o1 = 0.f, o2 = 0.f, o3 = 0.f;
        #pragma unroll
        for (int j = 0; j < 11; j++) {
            float w = s_w[j];
            o0 = fmaf(w, tv[j],     o0);
            o1 = fmaf(w, tv[j + 1], o1);
            o2 = fmaf(w, tv[j + 2], o2);
            o3 = fmaf(w, tv[j + 3], o3);
        }
        res[q][0] = o0; res[q][1] = o1; res[q][2] = o2; res[q][3] = o3;
    }

    float ssum = 0.f;
    #pragma unroll
    for (int k = 0; k < 4; k++) {
        float a = res[0][k], b = res[1][k];
        float a2v = a * a, b2v = b * b, ab = a * b;
        float sx2 = res[2][k] - a2v;
        float sy2 = res[3][k] - b2v;
        float sxy = res[4][k] - ab;
        float num = (2.f * ab  + SSIM_C1) * (2.f * sxy + SSIM_C2);
        float den = (a2v + b2v + SSIM_C1) * (sx2 + sy2 + SSIM_C2);
        ssum += __fdividef(num, den);
    }

    // ---- block reduction (deterministic, no float atomics) ----
    #pragma unroll
    for (int o = 16; o > 0; o >>= 1)
        ssum += __shfl_down_sync(0xffffffffu, ssum, o);
    const int wid = tid >> 5, lane = tid & 31;
    if (lane == 0) warpSums[wid] = ssum;
    __syncthreads();
    if (tid == 0) {
        float tot = 0.f;
        #pragma unroll
        for (int i = 0; i < 8; i++) tot += warpSums[i];
        int bid = bx + 16 * (by + 64 * bz);
        g_partial[bid] = tot;
        __threadfence();
        int prev = atomicAdd(&g_count, 1);
        s_isLast = (prev == NBLOCKS - 1);
    }
    __syncthreads();

    // ---- last block folds the global mean ----
    if (s_isLast) {
        __shared__ double dsum[8];
        const float4* p4 = (const float4*)g_partial;   // 4096 float4
        double s = 0.0;
        #pragma unroll
        for (int i = 0; i < 16; i++) {
            float4 v = p4[tid + i * 256];
            s += (double)v.x + (double)v.y + (double)v.z + (double)v.w;
        }
        #pragma unroll
        for (int o = 16; o > 0; o >>= 1)
            s += __shfl_down_sync(0xffffffffu, s, o);
        if (lane == 0) dsum[wid] = s;
        __syncthreads();
        if (tid == 0) {
            double t = 0.0;
            #pragma unroll
            for (int i = 0; i < 8; i++) t += dsum[i];
            out[0] = (float)(t / 16777216.0);
            g_count = 0;   // reset for next graph replay
        }
    }
}

extern "C" void kernel_launch(void* const* d_in, const int* in_sizes, int n_in,
                              void* d_out, int out_size)
{
    const float* img1 = (const float*)d_in[0];
    const float* img2 = (const float*)d_in[1];
    const float* kw   = (const float*)d_in[2];
    float* out = (float*)d_out;

    dim3 grid(16, 64, 16);   // 1024/64 x-tiles, 1024/16 y-tiles, 16 batch
    ssim_main<<<grid, 256>>>(img1, img2, kw, out);
}

// round 5
// speedup vs baseline: 1.1753x; 1.0315x over previous
#include <cuda_runtime.h>

#define SSIM_C1 1e-4f
#define SSIM_C2 9e-4f

// tile geometry: 64 x 16 outputs per block
#define TW 64
#define TH 16
#define HR 26            // halo rows (TH + 10)
#define RS 64            // hbuf row stride in floats
#define PS (HR * RS)     // plane stride = 1664 floats
#define NBLOCKS (16*64*16)

typedef unsigned long long u64;

__device__ __align__(16) float g_partial[NBLOCKS];
__device__ int g_count = 0;

// 11-tap gaussian (size=11, sigma=1.5), normalized; symmetric
__device__ __forceinline__ float gw(int i) {
    const float W[6] = {0.00102838f, 0.00759876f, 0.03600080f,
                        0.10936070f, 0.21300556f, 0.26601172f};
    return W[(i < 6) ? i : (10 - i)];
}

__device__ __forceinline__ u64 fma2(u64 a, u64 b, u64 c) {
    u64 d;
    asm("fma.rn.f32x2 %0, %1, %2, %3;" : "=l"(d) : "l"(a), "l"(b), "l"(c));
    return d;
}
__device__ __forceinline__ u64 dup2(float w) {
    u64 r;
    asm("mov.b64 %0, {%1, %1};" : "=l"(r) : "f"(w));
    return r;
}
__device__ __forceinline__ void unpack2(u64 v, float& lo, float& hi) {
    asm("mov.b64 {%0, %1}, %2;" : "=f"(lo), "=f"(hi) : "l"(v));
}

// scatter one input position i (0..17) into the 8 horizontal-conv accumulators
__device__ __forceinline__ void hacc(int i, float xa, float yb, float acc[5][8]) {
    float xx = xa * xa, yy = yb * yb, xy = xa * yb;
    #pragma unroll
    for (int c = 0; c < 8; c++) {
        int wi = i - c;
        if (wi >= 0 && wi <= 10) {
            float w = gw(wi);
            acc[0][c] = fmaf(xa, w, acc[0][c]);
            acc[1][c] = fmaf(yb, w, acc[1][c]);
            acc[2][c] = fmaf(xx, w, acc[2][c]);
            acc[3][c] = fmaf(yy, w, acc[3][c]);
            acc[4][c] = fmaf(xy, w, acc[4][c]);
        }
    }
}

__device__ __forceinline__ float ssim_px(float a, float b, float exx, float eyy, float exy) {
    float a2 = a * a, b2 = b * b, ab = a * b;
    float sx2 = exx - a2;
    float sy2 = eyy - b2;
    float sxy = exy - ab;
    float num = (2.f * ab  + SSIM_C1) * (2.f * sxy + SSIM_C2);
    float den = (a2 + b2 + SSIM_C1) * (sx2 + sy2 + SSIM_C2);
    return __fdividef(num, den);
}

__global__ __launch_bounds__(256) void ssim_main(
    const float* __restrict__ img1,
    const float* __restrict__ img2,
    float* __restrict__ out)
{
    __shared__ __align__(16) float hb[5 * PS];   // 5 horizontally-convolved planes
    __shared__ float warpSums[8];
    __shared__ int s_isLast;

    const int tid = threadIdx.x;
    const int bx = blockIdx.x, by = blockIdx.y, bz = blockIdx.z;
    const int row0 = by * TH;
    const int col0 = bx * TW;

    // ================= pass 1: horizontal conv, gmem -> registers -> hbuf =================
    // item = halo row r (0..25) x col-group g (0..7, 8 output cols each). 208 items.
    if (tid < 208) {
        int r = tid >> 3, g = tid & 7;
        int gr = row0 - 5 + r;
        float acc[5][8];
        #pragma unroll
        for (int q = 0; q < 5; q++)
            #pragma unroll
            for (int c = 0; c < 8; c++) acc[q][c] = 0.f;

        if ((unsigned)gr < 1024u) {
            const float* p1 = img1 + (size_t)bz * 1048576u + (size_t)gr * 1024u;
            const float* p2 = img2 + (size_t)bz * 1048576u + (size_t)gr * 1024u;
            int gb = col0 + 8 * g - 8;   // aligned window base; positions i=0..17 at gb+3..gb+20
            bool fast = (gb >= 0) && (gb + 24 <= 1024);
            if (fast) {
                #pragma unroll
                for (int m = 0; m < 6; m++) {
                    float4 av = *(const float4*)(p1 + gb + 4 * m);
                    float4 bv = *(const float4*)(p2 + gb + 4 * m);
                    int i0 = 4 * m - 3;
                    if (i0 + 0 >= 0 && i0 + 0 <= 17) hacc(i0 + 0, av.x, bv.x, acc);
                    if (i0 + 1 >= 0 && i0 + 1 <= 17) hacc(i0 + 1, av.y, bv.y, acc);
                    if (i0 + 2 >= 0 && i0 + 2 <= 17) hacc(i0 + 2, av.z, bv.z, acc);
                    if (i0 + 3 >= 0 && i0 + 3 <= 17) hacc(i0 + 3, av.w, bv.w, acc);
                }
            } else {
                #pragma unroll
                for (int i = 0; i < 18; i++) {
                    int gc = gb + 3 + i;
                    bool ok = (unsigned)gc < 1024u;
                    float xa = ok ? p1[gc] : 0.f;
                    float yb = ok ? p2[gc] : 0.f;
                    hacc(i, xa, yb, acc);
                }
            }
        }
        int sb = r * RS + 8 * g;
        #pragma unroll
        for (int q = 0; q < 5; q++) {
            *(float4*)&hb[q * PS + sb]     = make_float4(acc[q][0], acc[q][1], acc[q][2], acc[q][3]);
            *(float4*)&hb[q * PS + sb + 4] = make_float4(acc[q][4], acc[q][5], acc[q][6], acc[q][7]);
        }
    }
    __syncthreads();

    // ================= pass 2: vertical conv (packed f32x2) + SSIM =================
    // item = col-pair p (0..31) x row-chunk c (0..3, 4 output rows). 128 items.
    float ssum = 0.f;
    if (tid < 128) {
        int p = tid & 31, c = tid >> 5;
        u64 A[5][4];
        #pragma unroll
        for (int q = 0; q < 5; q++)
            #pragma unroll
            for (int j = 0; j < 4; j++) A[q][j] = 0;

        #pragma unroll
        for (int k = 0; k < 14; k++) {
            int row = 4 * c + k;
            #pragma unroll
            for (int q = 0; q < 5; q++) {
                u64 v = *(const u64*)&hb[q * PS + row * RS + 2 * p];
                #pragma unroll
                for (int j = 0; j < 4; j++) {
                    int wi = k - j;
                    if (wi >= 0 && wi <= 10)
                        A[q][j] = fma2(dup2(gw(wi)), v, A[q][j]);
                }
            }
        }
        #pragma unroll
        for (int j = 0; j < 4; j++) {
            float mx0, mx1, my0, my1, xx0, xx1, yy0, yy1, xy0, xy1;
            unpack2(A[0][j], mx0, mx1);
            unpack2(A[1][j], my0, my1);
            unpack2(A[2][j], xx0, xx1);
            unpack2(A[3][j], yy0, yy1);
            unpack2(A[4][j], xy0, xy1);
            ssum += ssim_px(mx0, my0, xx0, yy0, xy0);
            ssum += ssim_px(mx1, my1, xx1, yy1, xy1);
        }
    }

    // ================= block reduction (deterministic) =================
    #pragma unroll
    for (int o = 16; o > 0; o >>= 1)
        ssum += __shfl_down_sync(0xffffffffu, ssum, o);
    const int wid = tid >> 5, lane = tid & 31;
    if (lane == 0) warpSums[wid] = ssum;
    __syncthreads();
    if (tid == 0) {
        float tot = 0.f;
        #pragma unroll
        for (int i = 0; i < 8; i++) tot += warpSums[i];
        int bid = bx + 16 * (by + 64 * bz);
        g_partial[bid] = tot;
        __threadfence();
        int prev = atomicAdd(&g_count, 1);
        s_isLast = (prev == NBLOCKS - 1);
    }
    __syncthreads();

    // ================= last block folds the global mean =================
    if (s_isLast) {
        __shared__ double dsum[8];
        const float4* p4 = (const float4*)g_partial;   // 4096 float4
        double s = 0.0;
        #pragma unroll
        for (int i = 0; i < 16; i++) {
            float4 v = p4[tid + i * 256];
            s += (double)v.x + (double)v.y + (double)v.z + (double)v.w;
        }
        #pragma unroll
        for (int o = 16; o > 0; o >>= 1)
            s += __shfl_down_sync(0xffffffffu, s, o);
        if (lane == 0) dsum[wid] = s;
        __syncthreads();
        if (tid == 0) {
            double t = 0.0;
            #pragma unroll
            for (int i = 0; i < 8; i++) t += dsum[i];
            out[0] = (float)(t / 16777216.0);
            g_count = 0;   // reset for next graph replay
        }
    }
}

extern "C" void kernel_launch(void* const* d_in, const int* in_sizes, int n_in,
                              void* d_out, int out_size)
{
    const float* img1 = (const float*)d_in[0];
    const float* img2 = (const float*)d_in[1];
    float* out = (float*)d_out;

    dim3 grid(16, 64, 16);   // 1024/64 x-tiles, 1024/16 y-tiles, 16 batch
    ssim_main<<<grid, 256>>>(img1, img2, out);
}

// round 6
// speedup vs baseline: 1.2646x; 1.0760x over previous
#include <cuda_runtime.h>

#define SSIM_C1 1e-4f
#define SSIM_C2 9e-4f

// tile geometry: 64 x 16 outputs per block
#define TW 64
#define TH 16
#define HR 26            // halo rows (TH + 10)
#define RS 66            // hbuf row stride in floats (bank-spread)
#define PS (HR * RS)     // plane stride
#define NBLOCKS (16*64*16)

typedef unsigned long long u64;

__device__ __align__(16) float g_partial[NBLOCKS];
__device__ int g_count = 0;

// 11-tap gaussian (size=11, sigma=1.5), normalized; symmetric
__device__ __forceinline__ float gw(int i) {
    const float W[6] = {0.00102838f, 0.00759876f, 0.03600080f,
                        0.10936070f, 0.21300556f, 0.26601172f};
    return W[(i < 6) ? i : (10 - i)];
}
__device__ __forceinline__ float gwz(int d) {
    return (d >= 0 && d <= 10) ? gw(d) : 0.f;
}

__device__ __forceinline__ u64 pack2(float lo, float hi) {
    u64 r;
    asm("mov.b64 %0, {%1, %2};" : "=l"(r) : "f"(lo), "f"(hi));
    return r;
}
__device__ __forceinline__ u64 dup2(float w) {
    u64 r;
    asm("mov.b64 %0, {%1, %1};" : "=l"(r) : "f"(w));
    return r;
}
__device__ __forceinline__ u64 fma2(u64 a, u64 b, u64 c) {
    u64 d;
    asm("fma.rn.f32x2 %0, %1, %2, %3;" : "=l"(d) : "l"(a), "l"(b), "l"(c));
    return d;
}
__device__ __forceinline__ u64 mul2(u64 a, u64 b) {
    u64 d;
    asm("mul.rn.f32x2 %0, %1, %2;" : "=l"(d) : "l"(a), "l"(b));
    return d;
}
__device__ __forceinline__ void unpack2(u64 v, float& lo, float& hi) {
    asm("mov.b64 {%0, %1}, %2;" : "=f"(lo), "=f"(hi) : "l"(v));
}

// packed adjacent-weight pair for output cols (2c2, 2c2+1): (W[d], W[d-1])
__device__ __forceinline__ u64 wpair(int d) {
    return pack2(gwz(d), gwz(d - 1));
}

// scatter one input position i (0..17) into 4 packed col-pair accumulators
__device__ __forceinline__ void hacc2(int i, float xa, float yb, u64 acc2[5][4]) {
    u64 x2 = dup2(xa), y2 = dup2(yb);
    u64 xx = mul2(x2, x2), yy = mul2(y2, y2), xy = mul2(x2, y2);
    #pragma unroll
    for (int c2 = 0; c2 < 4; c2++) {
        int d = i - 2 * c2;
        if (d >= 0 && d <= 11) {
            u64 wp = wpair(d);
            acc2[0][c2] = fma2(x2, wp, acc2[0][c2]);
            acc2[1][c2] = fma2(y2, wp, acc2[1][c2]);
            acc2[2][c2] = fma2(xx, wp, acc2[2][c2]);
            acc2[3][c2] = fma2(yy, wp, acc2[3][c2]);
            acc2[4][c2] = fma2(xy, wp, acc2[4][c2]);
        }
    }
}

__device__ __forceinline__ float ssim_px(float a, float b, float exx, float eyy, float exy) {
    float a2 = a * a, b2 = b * b, ab = a * b;
    float sx2 = exx - a2;
    float sy2 = eyy - b2;
    float sxy = exy - ab;
    float num = (2.f * ab  + SSIM_C1) * (2.f * sxy + SSIM_C2);
    float den = (a2 + b2 + SSIM_C1) * (sx2 + sy2 + SSIM_C2);
    return __fdividef(num, den);
}

__global__ __launch_bounds__(256, 4) void ssim_main(
    const float* __restrict__ img1,
    const float* __restrict__ img2,
    float* __restrict__ out)
{
    __shared__ __align__(16) float hb[5 * PS];   // 5 horizontally-convolved planes
    __shared__ float warpSums[8];
    __shared__ int s_isLast;

    const int tid = threadIdx.x;
    const int bx = blockIdx.x, by = blockIdx.y, bz = blockIdx.z;
    const int row0 = by * TH;
    const int col0 = bx * TW;

    // ========== pass 1: horizontal conv (packed), gmem -> regs -> hbuf ==========
    // item = halo row r (0..25) x col-group g (0..7, 8 output cols = 4 pairs)
    if (tid < 208) {
        int r = tid >> 3, g = tid & 7;
        int gr = row0 - 5 + r;
        u64 acc2[5][4];
        #pragma unroll
        for (int q = 0; q < 5; q++)
            #pragma unroll
            for (int c2 = 0; c2 < 4; c2++) acc2[q][c2] = 0;

        if ((unsigned)gr < 1024u) {
            const float* p1 = img1 + (size_t)bz * 1048576u + (size_t)gr * 1024u;
            const float* p2 = img2 + (size_t)bz * 1048576u + (size_t)gr * 1024u;
            int gb = col0 + 8 * g - 8;   // window: positions i=0..17 at cols gb+3..gb+20
            bool fast = (gb >= 0) && (gb + 24 <= 1024);
            if (fast) {
                #pragma unroll
                for (int m = 0; m < 6; m++) {
                    float4 av = *(const float4*)(p1 + gb + 4 * m);
                    float4 bv = *(const float4*)(p2 + gb + 4 * m);
                    int i0 = 4 * m - 3;
                    if (i0 + 0 >= 0 && i0 + 0 <= 17) hacc2(i0 + 0, av.x, bv.x, acc2);
                    if (i0 + 1 >= 0 && i0 + 1 <= 17) hacc2(i0 + 1, av.y, bv.y, acc2);
                    if (i0 + 2 >= 0 && i0 + 2 <= 17) hacc2(i0 + 2, av.z, bv.z, acc2);
                    if (i0 + 3 >= 0 && i0 + 3 <= 17) hacc2(i0 + 3, av.w, bv.w, acc2);
                }
            } else {
                #pragma unroll
                for (int i = 0; i < 18; i++) {
                    int gc = gb + 3 + i;
                    bool ok = (unsigned)gc < 1024u;
                    float xa = ok ? p1[gc] : 0.f;
                    float yb = ok ? p2[gc] : 0.f;
                    hacc2(i, xa, yb, acc2);
                }
            }
        }
        int sb = r * RS + 8 * g;
        #pragma unroll
        for (int q = 0; q < 5; q++)
            #pragma unroll
            for (int c2 = 0; c2 < 4; c2++)
                *(u64*)&hb[q * PS + sb + 2 * c2] = acc2[q][c2];
    }
    __syncthreads();

    // ========== pass 2: vertical conv (packed) + SSIM — 256 items, full util ==========
    // item = col-pair p (0..31) x 2-row chunk c (0..7)
    float ssum;
    {
        int p = tid & 31, c = tid >> 5;
        u64 A[5][2];
        #pragma unroll
        for (int q = 0; q < 5; q++) { A[q][0] = 0; A[q][1] = 0; }

        const float* hp = &hb[(2 * c) * RS + 2 * p];
        #pragma unroll
        for (int k = 0; k < 12; k++) {
            #pragma unroll
            for (int q = 0; q < 5; q++) {
                u64 v = *(const u64*)(hp + q * PS + k * RS);
                if (k <= 10) A[q][0] = fma2(dup2(gw(k)),     v, A[q][0]);
                if (k >= 1)  A[q][1] = fma2(dup2(gw(k - 1)), v, A[q][1]);
            }
        }
        ssum = 0.f;
        #pragma unroll
        for (int j = 0; j < 2; j++) {
            float mx0, mx1, my0, my1, xx0, xx1, yy0, yy1, xy0, xy1;
            unpack2(A[0][j], mx0, mx1);
            unpack2(A[1][j], my0, my1);
            unpack2(A[2][j], xx0, xx1);
            unpack2(A[3][j], yy0, yy1);
            unpack2(A[4][j], xy0, xy1);
            ssum += ssim_px(mx0, my0, xx0, yy0, xy0);
            ssum += ssim_px(mx1, my1, xx1, yy1, xy1);
        }
    }

    // ========== block reduction (deterministic) ==========
    #pragma unroll
    for (int o = 16; o > 0; o >>= 1)
        ssum += __shfl_down_sync(0xffffffffu, ssum, o);
    const int wid = tid >> 5, lane = tid & 31;
    if (lane == 0) warpSums[wid] = ssum;
    __syncthreads();
    if (tid == 0) {
        float tot = 0.f;
        #pragma unroll
        for (int i = 0; i < 8; i++) tot += warpSums[i];
        int bid = bx + 16 * (by + 64 * bz);
        g_partial[bid] = tot;
        __threadfence();
        int prev = atomicAdd(&g_count, 1);
        s_isLast = (prev == NBLOCKS - 1);
    }
    __syncthreads();

    // ========== last block folds the global mean ==========
    if (s_isLast) {
        __shared__ double dsum[8];
        const float4* p4 = (const float4*)g_partial;   // 4096 float4
        double s = 0.0;
        #pragma unroll
        for (int i = 0; i < 16; i++) {
            float4 v = p4[tid + i * 256];
            s += (double)v.x + (double)v.y + (double)v.z + (double)v.w;
        }
        #pragma unroll
        for (int o = 16; o > 0; o >>= 1)
            s += __shfl_down_sync(0xffffffffu, s, o);
        if (lane == 0) dsum[wid] = s;
        __syncthreads();
        if (tid == 0) {
            double t = 0.0;
            #pragma unroll
            for (int i = 0; i < 8; i++) t += dsum[i];
            out[0] = (float)(t / 16777216.0);
            g_count = 0;   // reset for next graph replay
        }
    }
}

extern "C" void kernel_launch(void* const* d_in, const int* in_sizes, int n_in,
                              void* d_out, int out_size)
{
    const float* img1 = (const float*)d_in[0];
    const float* img2 = (const float*)d_in[1];
    float* out = (float*)d_out;

    dim3 grid(16, 64, 16);   // 1024/64 x-tiles, 1024/16 y-tiles, 16 batch
    ssim_main<<<grid, 256>>>(img1, img2, out);
}

// round 7
// speedup vs baseline: 1.4013x; 1.1081x over previous
#include <cuda_runtime.h>

#define SSIM_C1 1e-4f
#define SSIM_C2 9e-4f

// tile geometry: 64 x 32 outputs per block
#define TW 64
#define TH 32
#define HR 42            // halo rows (TH + 10)
#define RS 66            // hbuf row stride in floats (bank-spread)
#define PS (HR * RS)     // plane stride = 2772 floats
#define HB_BYTES (5 * PS * 4)
#define NBLOCKS (16*32*16)

typedef unsigned long long u64;

__device__ __align__(16) float g_partial[NBLOCKS];
__device__ int g_count = 0;

// 11-tap gaussian (size=11, sigma=1.5), normalized; symmetric
__device__ __forceinline__ float gw(int i) {
    const float W[6] = {0.00102838f, 0.00759876f, 0.03600080f,
                        0.10936070f, 0.21300556f, 0.26601172f};
    return W[(i < 6) ? i : (10 - i)];
}
__device__ __forceinline__ float gwz(int d) {
    return (d >= 0 && d <= 10) ? gw(d) : 0.f;
}

__device__ __forceinline__ u64 pack2(float lo, float hi) {
    u64 r;
    asm("mov.b64 %0, {%1, %2};" : "=l"(r) : "f"(lo), "f"(hi));
    return r;
}
__device__ __forceinline__ u64 dup2(float w) {
    u64 r;
    asm("mov.b64 %0, {%1, %1};" : "=l"(r) : "f"(w));
    return r;
}
__device__ __forceinline__ u64 fma2(u64 a, u64 b, u64 c) {
    u64 d;
    asm("fma.rn.f32x2 %0, %1, %2, %3;" : "=l"(d) : "l"(a), "l"(b), "l"(c));
    return d;
}
__device__ __forceinline__ u64 mul2(u64 a, u64 b) {
    u64 d;
    asm("mul.rn.f32x2 %0, %1, %2;" : "=l"(d) : "l"(a), "l"(b));
    return d;
}
__device__ __forceinline__ void unpack2(u64 v, float& lo, float& hi) {
    asm("mov.b64 {%0, %1}, %2;" : "=f"(lo), "=f"(hi) : "l"(v));
}

// packed adjacent-weight pair for output cols (2c2, 2c2+1): (W[d], W[d-1])
__device__ __forceinline__ u64 wpair(int d) {
    return pack2(gwz(d), gwz(d - 1));
}

// scatter one input position i (0..17) into 4 packed col-pair accumulators
__device__ __forceinline__ void hacc2(int i, float xa, float yb, u64 acc2[5][4]) {
    u64 x2 = dup2(xa), y2 = dup2(yb);
    u64 xx = mul2(x2, x2), yy = mul2(y2, y2), xy = mul2(x2, y2);
    #pragma unroll
    for (int c2 = 0; c2 < 4; c2++) {
        int d = i - 2 * c2;
        if (d >= 0 && d <= 11) {
            u64 wp = wpair(d);
            acc2[0][c2] = fma2(x2, wp, acc2[0][c2]);
            acc2[1][c2] = fma2(y2, wp, acc2[1][c2]);
            acc2[2][c2] = fma2(xx, wp, acc2[2][c2]);
            acc2[3][c2] = fma2(yy, wp, acc2[3][c2]);
            acc2[4][c2] = fma2(xy, wp, acc2[4][c2]);
        }
    }
}

__device__ __forceinline__ float ssim_px(float a, float b, float exx, float eyy, float exy) {
    float a2 = a * a, b2 = b * b, ab = a * b;
    float sx2 = exx - a2;
    float sy2 = eyy - b2;
    float sxy = exy - ab;
    float num = (2.f * ab  + SSIM_C1) * (2.f * sxy + SSIM_C2);
    float den = (a2 + b2 + SSIM_C1) * (sx2 + sy2 + SSIM_C2);
    return __fdividef(num, den);
}

__global__ __launch_bounds__(256, 4) void ssim_main(
    const float* __restrict__ img1,
    const float* __restrict__ img2,
    float* __restrict__ out)
{
    extern __shared__ __align__(16) float hb[];   // 5 horizontally-convolved planes
    __shared__ float warpSums[8];
    __shared__ int s_isLast;

    const int tid = threadIdx.x;
    const int bx = blockIdx.x, by = blockIdx.y, bz = blockIdx.z;
    const int row0 = by * TH;
    const int col0 = bx * TW;

    // ========== pass 1: horizontal conv (packed), gmem -> regs -> hbuf ==========
    // item = halo row r (0..41) x col-group g (0..7, 8 output cols = 4 pairs) -> 336 items
    for (int t = tid; t < HR * 8; t += 256) {
        int r = t >> 3, g = t & 7;
        int gr = row0 - 5 + r;
        u64 acc2[5][4];
        #pragma unroll
        for (int q = 0; q < 5; q++)
            #pragma unroll
            for (int c2 = 0; c2 < 4; c2++) acc2[q][c2] = 0;

        if ((unsigned)gr < 1024u) {
            const float* p1 = img1 + (size_t)bz * 1048576u + (size_t)gr * 1024u;
            const float* p2 = img2 + (size_t)bz * 1048576u + (size_t)gr * 1024u;
            int gb = col0 + 8 * g - 8;   // window: positions i=0..17 at cols gb+3..gb+20
            bool fast = (gb >= 0) && (gb + 24 <= 1024);
            if (fast) {
                #pragma unroll
                for (int m = 0; m < 6; m++) {
                    float4 av = *(const float4*)(p1 + gb + 4 * m);
                    float4 bv = *(const float4*)(p2 + gb + 4 * m);
                    int i0 = 4 * m - 3;
                    if (i0 + 0 >= 0 && i0 + 0 <= 17) hacc2(i0 + 0, av.x, bv.x, acc2);
                    if (i0 + 1 >= 0 && i0 + 1 <= 17) hacc2(i0 + 1, av.y, bv.y, acc2);
                    if (i0 + 2 >= 0 && i0 + 2 <= 17) hacc2(i0 + 2, av.z, bv.z, acc2);
                    if (i0 + 3 >= 0 && i0 + 3 <= 17) hacc2(i0 + 3, av.w, bv.w, acc2);
                }
            } else {
                #pragma unroll
                for (int i = 0; i < 18; i++) {
                    int gc = gb + 3 + i;
                    bool ok = (unsigned)gc < 1024u;
                    float xa = ok ? p1[gc] : 0.f;
                    float yb = ok ? p2[gc] : 0.f;
                    hacc2(i, xa, yb, acc2);
                }
            }
        }
        int sb = r * RS + 8 * g;
        #pragma unroll
        for (int q = 0; q < 5; q++)
            #pragma unroll
            for (int c2 = 0; c2 < 4; c2++)
                *(u64*)&hb[q * PS + sb + 2 * c2] = acc2[q][c2];
    }
    __syncthreads();

    // ========== pass 2: vertical conv (packed, R=4) + SSIM — 256 items, full util ==========
    // item = col-pair p (0..31) x 4-row chunk c (0..7)
    float ssum;
    {
        int p = tid & 31, c = tid >> 5;
        u64 A[5][4];
        #pragma unroll
        for (int q = 0; q < 5; q++)
            #pragma unroll
            for (int j = 0; j < 4; j++) A[q][j] = 0;

        const float* hp = &hb[(4 * c) * RS + 2 * p];
        #pragma unroll
        for (int k = 0; k < 14; k++) {
            #pragma unroll
            for (int q = 0; q < 5; q++) {
                u64 v = *(const u64*)(hp + q * PS + k * RS);
                #pragma unroll
                for (int j = 0; j < 4; j++) {
                    int wi = k - j;
                    if (wi >= 0 && wi <= 10)
                        A[q][j] = fma2(dup2(gw(wi)), v, A[q][j]);
                }
            }
        }
        ssum = 0.f;
        #pragma unroll
        for (int j = 0; j < 4; j++) {
            float mx0, mx1, my0, my1, xx0, xx1, yy0, yy1, xy0, xy1;
            unpack2(A[0][j], mx0, mx1);
            unpack2(A[1][j], my0, my1);
            unpack2(A[2][j], xx0, xx1);
            unpack2(A[3][j], yy0, yy1);
            unpack2(A[4][j], xy0, xy1);
            ssum += ssim_px(mx0, my0, xx0, yy0, xy0);
            ssum += ssim_px(mx1, my1, xx1, yy1, xy1);
        }
    }

    // ========== block reduction (deterministic) ==========
    #pragma unroll
    for (int o = 16; o > 0; o >>= 1)
        ssum += __shfl_down_sync(0xffffffffu, ssum, o);
    const int wid = tid >> 5, lane = tid & 31;
    if (lane == 0) warpSums[wid] = ssum;
    __syncthreads();
    if (tid == 0) {
        float tot = 0.f;
        #pragma unroll
        for (int i = 0; i < 8; i++) tot += warpSums[i];
        int bid = bx + 16 * (by + 32 * bz);
        g_partial[bid] = tot;
        __threadfence();
        int prev = atomicAdd(&g_count, 1);
        s_isLast = (prev == NBLOCKS - 1);
    }
    __syncthreads();

    // ========== last block folds the global mean ==========
    if (s_isLast) {
        __shared__ double dsum[8];
        const float4* p4 = (const float4*)g_partial;   // 2048 float4
        double s = 0.0;
        #pragma unroll
        for (int i = 0; i < 8; i++) {
            float4 v = p4[tid + i * 256];
            s += (double)v.x + (double)v.y + (double)v.z + (double)v.w;
        }
        #pragma unroll
        for (int o = 16; o > 0; o >>= 1)
            s += __shfl_down_sync(0xffffffffu, s, o);
        if (lane == 0) dsum[wid] = s;
        __syncthreads();
        if (tid == 0) {
            double t = 0.0;
            #pragma unroll
            for (int i = 0; i < 8; i++) t += dsum[i];
            out[0] = (float)(t / 16777216.0);
            g_count = 0;   // reset for next graph replay
        }
    }
}

extern "C" void kernel_launch(void* const* d_in, const int* in_sizes, int n_in,
                              void* d_out, int out_size)
{
    const float* img1 = (const float*)d_in[0];
    const float* img2 = (const float*)d_in[1];
    float* out = (float*)d_out;

    cudaFuncSetAttribute(ssim_main, cudaFuncAttributeMaxDynamicSharedMemorySize, HB_BYTES);

    dim3 grid(16, 32, 16);   // 1024/64 x-tiles, 1024/32 y-tiles, 16 batch
    ssim_main<<<grid, 256, HB_BYTES>>>(img1, img2, out);
}

// round 8
// speedup vs baseline: 1.5401x; 1.0991x over previous
#include <cuda_runtime.h>

#define SSIM_C1 1e-4f
#define SSIM_C2 9e-4f

// tile geometry: 64 x 32 outputs per block
#define TW 64
#define TH 32
#define HR 42            // halo rows (TH + 10)
#define RS2 33           // hbuf row stride in half2 units (33 col-pairs)
#define PS2 (HR * RS2)   // plane stride in half2 units
#define HB_BYTES (5 * PS2 * 4)
#define NBLOCKS (16*32*16)

typedef unsigned long long u64;
typedef unsigned int u32;

__device__ __align__(16) float g_partial[NBLOCKS];
__device__ int g_count = 0;

// 11-tap gaussian (size=11, sigma=1.5), normalized; symmetric
__device__ __forceinline__ float gw(int i) {
    const float W[6] = {0.00102838f, 0.00759876f, 0.03600080f,
                        0.10936070f, 0.21300556f, 0.26601172f};
    return W[(i < 6) ? i : (10 - i)];
}
__device__ __forceinline__ float gwz(int d) {
    return (d >= 0 && d <= 10) ? gw(d) : 0.f;
}

__device__ __forceinline__ u64 pack2(float lo, float hi) {
    u64 r;
    asm("mov.b64 %0, {%1, %2};" : "=l"(r) : "f"(lo), "f"(hi));
    return r;
}
__device__ __forceinline__ u64 dup2(float w) {
    u64 r;
    asm("mov.b64 %0, {%1, %1};" : "=l"(r) : "f"(w));
    return r;
}
__device__ __forceinline__ u64 fma2(u64 a, u64 b, u64 c) {
    u64 d;
    asm("fma.rn.f32x2 %0, %1, %2, %3;" : "=l"(d) : "l"(a), "l"(b), "l"(c));
    return d;
}
__device__ __forceinline__ u64 mul2(u64 a, u64 b) {
    u64 d;
    asm("mul.rn.f32x2 %0, %1, %2;" : "=l"(d) : "l"(a), "l"(b));
    return d;
}
__device__ __forceinline__ void unpack2(u64 v, float& lo, float& hi) {
    asm("mov.b64 {%0, %1}, %2;" : "=f"(lo), "=f"(hi) : "l"(v));
}

// pack f32x2 (u64) -> f16x2 (u32), lanes preserved (lo->lo, hi->hi)
__device__ __forceinline__ u32 f2h2(u64 v) {
    u32 d;
    asm("{\n\t"
        ".reg .f32 a, b;\n\t"
        "mov.b64 {a, b}, %1;\n\t"
        "cvt.rn.f16x2.f32 %0, b, a;\n\t"   // first src -> hi, second -> lo
        "}" : "=r"(d) : "l"(v));
    return d;
}
// unpack f16x2 (u32) -> f32x2 (u64), lanes preserved
__device__ __forceinline__ u64 h2f2(u32 h) {
    u64 r;
    asm("{\n\t"
        ".reg .b16 lo, hi;\n\t"
        ".reg .f32 a, b;\n\t"
        "mov.b32 {lo, hi}, %1;\n\t"
        "cvt.f32.f16 a, lo;\n\t"
        "cvt.f32.f16 b, hi;\n\t"
        "mov.b64 %0, {a, b};\n\t"
        "}" : "=l"(r) : "r"(h));
    return r;
}

// packed adjacent-weight pair for output cols (2c2, 2c2+1): (W[d], W[d-1])
__device__ __forceinline__ u64 wpair(int d) {
    return pack2(gwz(d), gwz(d - 1));
}

// scatter one input position i (0..17) into 4 packed col-pair accumulators
__device__ __forceinline__ void hacc2(int i, float xa, float yb, u64 acc2[5][4]) {
    u64 x2 = dup2(xa), y2 = dup2(yb);
    u64 xx = mul2(x2, x2), yy = mul2(y2, y2), xy = mul2(x2, y2);
    #pragma unroll
    for (int c2 = 0; c2 < 4; c2++) {
        int d = i - 2 * c2;
        if (d >= 0 && d <= 11) {
            u64 wp = wpair(d);
            acc2[0][c2] = fma2(x2, wp, acc2[0][c2]);
            acc2[1][c2] = fma2(y2, wp, acc2[1][c2]);
            acc2[2][c2] = fma2(xx, wp, acc2[2][c2]);
            acc2[3][c2] = fma2(yy, wp, acc2[3][c2]);
            acc2[4][c2] = fma2(xy, wp, acc2[4][c2]);
        }
    }
}

__device__ __forceinline__ float ssim_px(float a, float b, float exx, float eyy, float exy) {
    float a2 = a * a, b2 = b * b, ab = a * b;
    float sx2 = exx - a2;
    float sy2 = eyy - b2;
    float sxy = exy - ab;
    float num = (2.f * ab  + SSIM_C1) * (2.f * sxy + SSIM_C2);
    float den = (a2 + b2 + SSIM_C1) * (sx2 + sy2 + SSIM_C2);
    return __fdividef(num, den);
}

__global__ __launch_bounds__(256, 4) void ssim_main(
    const float* __restrict__ img1,
    const float* __restrict__ img2,
    float* __restrict__ out)
{
    extern __shared__ __align__(16) u32 hb[];   // 5 planes of f16x2 col-pairs
    __shared__ float warpSums[8];
    __shared__ int s_isLast;

    const int tid = threadIdx.x;
    const int bx = blockIdx.x, by = blockIdx.y, bz = blockIdx.z;
    const int row0 = by * TH;
    const int col0 = bx * TW;

    // ========== pass 1: horizontal conv (packed f32), gmem -> regs -> f16x2 hbuf ==========
    // item = halo row r (0..41) x col-group g (0..7, 8 output cols = 4 pairs) -> 336 items
    for (int t = tid; t < HR * 8; t += 256) {
        int r = t >> 3, g = t & 7;
        int gr = row0 - 5 + r;
        u64 acc2[5][4];
        #pragma unroll
        for (int q = 0; q < 5; q++)
            #pragma unroll
            for (int c2 = 0; c2 < 4; c2++) acc2[q][c2] = 0;

        if ((unsigned)gr < 1024u) {
            const float* p1 = img1 + (size_t)bz * 1048576u + (size_t)gr * 1024u;
            const float* p2 = img2 + (size_t)bz * 1048576u + (size_t)gr * 1024u;
            int gb = col0 + 8 * g - 8;   // window: positions i=0..17 at cols gb+3..gb+20
            bool fast = (gb >= 0) && (gb + 24 <= 1024);
            if (fast) {
                #pragma unroll
                for (int m = 0; m < 6; m++) {
                    float4 av = *(const float4*)(p1 + gb + 4 * m);
                    float4 bv = *(const float4*)(p2 + gb + 4 * m);
                    int i0 = 4 * m - 3;
                    if (i0 + 0 >= 0 && i0 + 0 <= 17) hacc2(i0 + 0, av.x, bv.x, acc2);
                    if (i0 + 1 >= 0 && i0 + 1 <= 17) hacc2(i0 + 1, av.y, bv.y, acc2);
                    if (i0 + 2 >= 0 && i0 + 2 <= 17) hacc2(i0 + 2, av.z, bv.z, acc2);
                    if (i0 + 3 >= 0 && i0 + 3 <= 17) hacc2(i0 + 3, av.w, bv.w, acc2);
                }
            } else {
                #pragma unroll
                for (int i = 0; i < 18; i++) {
                    int gc = gb + 3 + i;
                    bool ok = (unsigned)gc < 1024u;
                    float xa = ok ? p1[gc] : 0.f;
                    float yb = ok ? p2[gc] : 0.f;
                    hacc2(i, xa, yb, acc2);
                }
            }
        }
        int sb = r * RS2 + 4 * g;
        #pragma unroll
        for (int q = 0; q < 5; q++)
            #pragma unroll
            for (int c2 = 0; c2 < 4; c2++)
                hb[q * PS2 + sb + c2] = f2h2(acc2[q][c2]);
    }
    __syncthreads();

    // ========== pass 2: vertical conv (f16x2 loads -> f32x2 fma, R=4) + SSIM ==========
    // item = col-pair p (0..31) x 4-row chunk c (0..7) -> 256 items, full util
    float ssum;
    {
        int p = tid & 31, c = tid >> 5;
        u64 A[5][4];
        #pragma unroll
        for (int q = 0; q < 5; q++)
            #pragma unroll
            for (int j = 0; j < 4; j++) A[q][j] = 0;

        const u32* hp = &hb[(4 * c) * RS2 + p];
        #pragma unroll
        for (int k = 0; k < 14; k++) {
            #pragma unroll
            for (int q = 0; q < 5; q++) {
                u64 v = h2f2(hp[q * PS2 + k * RS2]);
                #pragma unroll
                for (int j = 0; j < 4; j++) {
                    int wi = k - j;
                    if (wi >= 0 && wi <= 10)
                        A[q][j] = fma2(dup2(gw(wi)), v, A[q][j]);
                }
            }
        }
        ssum = 0.f;
        #pragma unroll
        for (int j = 0; j < 4; j++) {
            float mx0, mx1, my0, my1, xx0, xx1, yy0, yy1, xy0, xy1;
            unpack2(A[0][j], mx0, mx1);
            unpack2(A[1][j], my0, my1);
            unpack2(A[2][j], xx0, xx1);
            unpack2(A[3][j], yy0, yy1);
            unpack2(A[4][j], xy0, xy1);
            ssum += ssim_px(mx0, my0, xx0, yy0, xy0);
            ssum += ssim_px(mx1, my1, xx1, yy1, xy1);
        }
    }

    // ========== block reduction (deterministic) ==========
    #pragma unroll
    for (int o = 16; o > 0; o >>= 1)
        ssum += __shfl_down_sync(0xffffffffu, ssum, o);
    const int wid = tid >> 5, lane = tid & 31;
    if (lane == 0) warpSums[wid] = ssum;
    __syncthreads();
    if (tid == 0) {
        float tot = 0.f;
        #pragma unroll
        for (int i = 0; i < 8; i++) tot += warpSums[i];
        int bid = bx + 16 * (by + 32 * bz);
        g_partial[bid] = tot;
        __threadfence();
        int prev = atomicAdd(&g_count, 1);
        s_isLast = (prev == NBLOCKS - 1);
    }
    __syncthreads();

    // ========== last block folds the global mean ==========
    if (s_isLast) {
        __shared__ double dsum[8];
        const float4* p4 = (const float4*)g_partial;   // 2048 float4
        double s = 0.0;
        #pragma unroll
        for (int i = 0; i < 8; i++) {
            float4 v = p4[tid + i * 256];
            s += (double)v.x + (double)v.y + (double)v.z + (double)v.w;
        }
        #pragma unroll
        for (int o = 16; o > 0; o >>= 1)
            s += __shfl_down_sync(0xffffffffu, s, o);
        if (lane == 0) dsum[wid] = s;
        __syncthreads();
        if (tid == 0) {
            double t = 0.0;
            #pragma unroll
            for (int i = 0; i < 8; i++) t += dsum[i];
            out[0] = (float)(t / 16777216.0);
            g_count = 0;   // reset for next graph replay
        }
    }
}

extern "C" void kernel_launch(void* const* d_in, const int* in_sizes, int n_in,
                              void* d_out, int out_size)
{
    const float* img1 = (const float*)d_in[0];
    const float* img2 = (const float*)d_in[1];
    float* out = (float*)d_out;

    cudaFuncSetAttribute(ssim_main, cudaFuncAttributeMaxDynamicSharedMemorySize, HB_BYTES);

    dim3 grid(16, 32, 16);   // 1024/64 x-tiles, 1024/32 y-tiles, 16 batch
    ssim_main<<<grid, 256, HB_BYTES>>>(img1, img2, out);
}

// round 9
// speedup vs baseline: 1.6666x; 1.0821x over previous
#include <cuda_runtime.h>

#define SSIM_C1 1e-4f
#define SSIM_C2 9e-4f

// tile geometry: 64 x 64 outputs per block
#define TW 64
#define TH 64
#define HR 74            // halo rows (TH + 10)
#define RS2 33           // hbuf row stride in half2 units (33 col-pairs)
#define PS2 (HR * RS2)   // plane stride in half2 units
#define HB_BYTES (5 * PS2 * 4)
#define NBLOCKS (16*16*16)

typedef unsigned long long u64;
typedef unsigned int u32;

__device__ __align__(16) float g_partial[NBLOCKS];
__device__ int g_count = 0;

// 11-tap gaussian (size=11, sigma=1.5), normalized; symmetric
__device__ __forceinline__ float gw(int i) {
    const float W[6] = {0.00102838f, 0.00759876f, 0.03600080f,
                        0.10936070f, 0.21300556f, 0.26601172f};
    return W[(i < 6) ? i : (10 - i)];
}
__device__ __forceinline__ float gwz(int d) {
    return (d >= 0 && d <= 10) ? gw(d) : 0.f;
}

__device__ __forceinline__ u64 pack2(float lo, float hi) {
    u64 r;
    asm("mov.b64 %0, {%1, %2};" : "=l"(r) : "f"(lo), "f"(hi));
    return r;
}
__device__ __forceinline__ u64 dup2(float w) {
    u64 r;
    asm("mov.b64 %0, {%1, %1};" : "=l"(r) : "f"(w));
    return r;
}
__device__ __forceinline__ u64 fma2(u64 a, u64 b, u64 c) {
    u64 d;
    asm("fma.rn.f32x2 %0, %1, %2, %3;" : "=l"(d) : "l"(a), "l"(b), "l"(c));
    return d;
}
__device__ __forceinline__ u64 mul2(u64 a, u64 b) {
    u64 d;
    asm("mul.rn.f32x2 %0, %1, %2;" : "=l"(d) : "l"(a), "l"(b));
    return d;
}
__device__ __forceinline__ void unpack2(u64 v, float& lo, float& hi) {
    asm("mov.b64 {%0, %1}, %2;" : "=f"(lo), "=f"(hi) : "l"(v));
}

// pack f32x2 (u64) -> f16x2 (u32), lanes preserved (lo->lo, hi->hi)
__device__ __forceinline__ u32 f2h2(u64 v) {
    u32 d;
    asm("{\n\t"
        ".reg .f32 a, b;\n\t"
        "mov.b64 {a, b}, %1;\n\t"
        "cvt.rn.f16x2.f32 %0, b, a;\n\t"
        "}" : "=r"(d) : "l"(v));
    return d;
}
// unpack f16x2 (u32) -> f32x2 (u64), lanes preserved
__device__ __forceinline__ u64 h2f2(u32 h) {
    u64 r;
    asm("{\n\t"
        ".reg .b16 lo, hi;\n\t"
        ".reg .f32 a, b;\n\t"
        "mov.b32 {lo, hi}, %1;\n\t"
        "cvt.f32.f16 a, lo;\n\t"
        "cvt.f32.f16 b, hi;\n\t"
        "mov.b64 %0, {a, b};\n\t"
        "}" : "=l"(r) : "r"(h));
    return r;
}

// packed adjacent-weight pair for output cols (2c2, 2c2+1): (W[d], W[d-1])
__device__ __forceinline__ u64 wpair(int d) {
    return pack2(gwz(d), gwz(d - 1));
}

// scatter one input position i (0..17) into 4 packed col-pair accumulators
__device__ __forceinline__ void hacc2(int i, float xa, float yb, u64 acc2[5][4]) {
    u64 x2 = dup2(xa), y2 = dup2(yb);
    u64 xx = mul2(x2, x2), yy = mul2(y2, y2), xy = mul2(x2, y2);
    #pragma unroll
    for (int c2 = 0; c2 < 4; c2++) {
        int d = i - 2 * c2;
        if (d >= 0 && d <= 11) {
            u64 wp = wpair(d);
            acc2[0][c2] = fma2(x2, wp, acc2[0][c2]);
            acc2[1][c2] = fma2(y2, wp, acc2[1][c2]);
            acc2[2][c2] = fma2(xx, wp, acc2[2][c2]);
            acc2[3][c2] = fma2(yy, wp, acc2[3][c2]);
            acc2[4][c2] = fma2(xy, wp, acc2[4][c2]);
        }
    }
}

__device__ __forceinline__ float ssim_px(float a, float b, float exx, float eyy, float exy) {
    float a2 = a * a, b2 = b * b, ab = a * b;
    float sx2 = exx - a2;
    float sy2 = eyy - b2;
    float sxy = exy - ab;
    float num = (2.f * ab  + SSIM_C1) * (2.f * sxy + SSIM_C2);
    float den = (a2 + b2 + SSIM_C1) * (sx2 + sy2 + SSIM_C2);
    return __fdividef(num, den);
}

__global__ __launch_bounds__(256, 4) void ssim_main(
    const float* __restrict__ img1,
    const float* __restrict__ img2,
    float* __restrict__ out)
{
    extern __shared__ __align__(16) u32 hb[];   // 5 planes of f16x2 col-pairs
    __shared__ float warpSums[8];
    __shared__ int s_isLast;

    const int tid = threadIdx.x;
    const int bx = blockIdx.x, by = blockIdx.y, bz = blockIdx.z;
    const int row0 = by * TH;
    const int col0 = bx * TW;

    // ========== pass 1: horizontal conv (packed f32), gmem -> regs -> f16x2 hbuf ==========
    // item = halo row r (0..73) x col-group g (0..7, 8 output cols = 4 pairs) -> 592 items
    for (int t = tid; t < HR * 8; t += 256) {
        int r = t >> 3, g = t & 7;
        int gr = row0 - 5 + r;
        u64 acc2[5][4];
        #pragma unroll
        for (int q = 0; q < 5; q++)
            #pragma unroll
            for (int c2 = 0; c2 < 4; c2++) acc2[q][c2] = 0;

        if ((unsigned)gr < 1024u) {
            const float* p1 = img1 + (size_t)bz * 1048576u + (size_t)gr * 1024u;
            const float* p2 = img2 + (size_t)bz * 1048576u + (size_t)gr * 1024u;
            int gb = col0 + 8 * g - 8;   // window: positions i=0..17 at cols gb+3..gb+20
            bool fast = (gb >= 0) && (gb + 24 <= 1024);
            if (fast) {
                #pragma unroll
                for (int m = 0; m < 6; m++) {
                    float4 av = *(const float4*)(p1 + gb + 4 * m);
                    float4 bv = *(const float4*)(p2 + gb + 4 * m);
                    int i0 = 4 * m - 3;
                    if (i0 + 0 >= 0 && i0 + 0 <= 17) hacc2(i0 + 0, av.x, bv.x, acc2);
                    if (i0 + 1 >= 0 && i0 + 1 <= 17) hacc2(i0 + 1, av.y, bv.y, acc2);
                    if (i0 + 2 >= 0 && i0 + 2 <= 17) hacc2(i0 + 2, av.z, bv.z, acc2);
                    if (i0 + 3 >= 0 && i0 + 3 <= 17) hacc2(i0 + 3, av.w, bv.w, acc2);
                }
            } else {
                #pragma unroll
                for (int i = 0; i < 18; i++) {
                    int gc = gb + 3 + i;
                    bool ok = (unsigned)gc < 1024u;
                    float xa = ok ? p1[gc] : 0.f;
                    float yb = ok ? p2[gc] : 0.f;
                    hacc2(i, xa, yb, acc2);
                }
            }
        }
        int sb = r * RS2 + 4 * g;
        #pragma unroll
        for (int q = 0; q < 5; q++)
            #pragma unroll
            for (int c2 = 0; c2 < 4; c2++)
                hb[q * PS2 + sb + c2] = f2h2(acc2[q][c2]);
    }
    __syncthreads();

    // ========== pass 2: vertical conv (f16x2 loads -> f32x2 fma, R=4) + SSIM ==========
    // item = col-pair p (0..31) x 4-row chunk c (0..15) -> 512 items, 2 per thread
    float ssum = 0.f;
    for (int it = tid; it < 512; it += 256) {
        int p = it & 31, c = it >> 5;
        u64 A[5][4];
        #pragma unroll
        for (int q = 0; q < 5; q++)
            #pragma unroll
            for (int j = 0; j < 4; j++) A[q][j] = 0;

        const u32* hp = &hb[(4 * c) * RS2 + p];
        #pragma unroll
        for (int k = 0; k < 14; k++) {
            #pragma unroll
            for (int q = 0; q < 5; q++) {
                u64 v = h2f2(hp[q * PS2 + k * RS2]);
                #pragma unroll
                for (int j = 0; j < 4; j++) {
                    int wi = k - j;
                    if (wi >= 0 && wi <= 10)
                        A[q][j] = fma2(dup2(gw(wi)), v, A[q][j]);
                }
            }
        }
        #pragma unroll
        for (int j = 0; j < 4; j++) {
            float mx0, mx1, my0, my1, xx0, xx1, yy0, yy1, xy0, xy1;
            unpack2(A[0][j], mx0, mx1);
            unpack2(A[1][j], my0, my1);
            unpack2(A[2][j], xx0, xx1);
            unpack2(A[3][j], yy0, yy1);
            unpack2(A[4][j], xy0, xy1);
            ssum += ssim_px(mx0, my0, xx0, yy0, xy0);
            ssum += ssim_px(mx1, my1, xx1, yy1, xy1);
        }
    }

    // ========== block reduction (deterministic) ==========
    #pragma unroll
    for (int o = 16; o > 0; o >>= 1)
        ssum += __shfl_down_sync(0xffffffffu, ssum, o);
    const int wid = tid >> 5, lane = tid & 31;
    if (lane == 0) warpSums[wid] = ssum;
    __syncthreads();
    if (tid == 0) {
        float tot = 0.f;
        #pragma unroll
        for (int i = 0; i < 8; i++) tot += warpSums[i];
        int bid = bx + 16 * (by + 16 * bz);
        g_partial[bid] = tot;
        __threadfence();
        int prev = atomicAdd(&g_count, 1);
        s_isLast = (prev == NBLOCKS - 1);
    }
    __syncthreads();

    // ========== last block folds the global mean ==========
    if (s_isLast) {
        __shared__ double dsum[8];
        const float4* p4 = (const float4*)g_partial;   // 1024 float4
        double s = 0.0;
        #pragma unroll
        for (int i = 0; i < 4; i++) {
            float4 v = p4[tid + i * 256];
            s += (double)v.x + (double)v.y + (double)v.z + (double)v.w;
        }
        #pragma unroll
        for (int o = 16; o > 0; o >>= 1)
            s += __shfl_down_sync(0xffffffffu, s, o);
        if (lane == 0) dsum[wid] = s;
        __syncthreads();
        if (tid == 0) {
            double t = 0.0;
            #pragma unroll
            for (int i = 0; i < 8; i++) t += dsum[i];
            out[0] = (float)(t / 16777216.0);
            g_count = 0;   // reset for next graph replay
        }
    }
}

extern "C" void kernel_launch(void* const* d_in, const int* in_sizes, int n_in,
                              void* d_out, int out_size)
{
    const float* img1 = (const float*)d_in[0];
    const float* img2 = (const float*)d_in[1];
    float* out = (float*)d_out;

    cudaFuncSetAttribute(ssim_main, cudaFuncAttributeMaxDynamicSharedMemorySize, HB_BYTES);

    dim3 grid(16, 16, 16);   // 1024/64 x-tiles, 1024/64 y-tiles, 16 batch
    ssim_main<<<grid, 256, HB_BYTES>>>(img1, img2, out);
}

// round 10
// speedup vs baseline: 2.0406x; 1.2244x over previous
#include <cuda_runtime.h>

#define SSIM_C1 1e-4f
#define SSIM_C2 9e-4f

// tile geometry: 64 x 64 outputs per block
#define TW 64
#define TH 64
#define HR 74            // halo rows (TH + 10)
#define RS2 33           // hbuf row stride in half2 units (33 col-pairs)
#define PS2 (HR * RS2)   // plane stride in half2 units
#define NPL 4            // planes: mu_s, mu_d, E[ss], E[dd]
#define HB_BYTES (NPL * PS2 * 4)
#define NBLOCKS (16*16*16)

typedef unsigned long long u64;
typedef unsigned int u32;

__device__ __align__(16) float g_partial[NBLOCKS];
__device__ int g_count = 0;

// 11-tap gaussian (size=11, sigma=1.5), normalized; symmetric
__device__ __forceinline__ float gw(int i) {
    const float W[6] = {0.00102838f, 0.00759876f, 0.03600080f,
                        0.10936070f, 0.21300556f, 0.26601172f};
    return W[(i < 6) ? i : (10 - i)];
}
__device__ __forceinline__ float gwz(int d) {
    return (d >= 0 && d <= 10) ? gw(d) : 0.f;
}

__device__ __forceinline__ u64 pack2(float lo, float hi) {
    u64 r;
    asm("mov.b64 %0, {%1, %2};" : "=l"(r) : "f"(lo), "f"(hi));
    return r;
}
__device__ __forceinline__ u64 dup2(float w) {
    u64 r;
    asm("mov.b64 %0, {%1, %1};" : "=l"(r) : "f"(w));
    return r;
}
__device__ __forceinline__ u64 fma2(u64 a, u64 b, u64 c) {
    u64 d;
    asm("fma.rn.f32x2 %0, %1, %2, %3;" : "=l"(d) : "l"(a), "l"(b), "l"(c));
    return d;
}
__device__ __forceinline__ u64 mul2(u64 a, u64 b) {
    u64 d;
    asm("mul.rn.f32x2 %0, %1, %2;" : "=l"(d) : "l"(a), "l"(b));
    return d;
}
__device__ __forceinline__ void unpack2(u64 v, float& lo, float& hi) {
    asm("mov.b64 {%0, %1}, %2;" : "=f"(lo), "=f"(hi) : "l"(v));
}

// pack f32x2 (u64) -> f16x2 (u32), lanes preserved
__device__ __forceinline__ u32 f2h2(u64 v) {
    u32 d;
    asm("{\n\t"
        ".reg .f32 a, b;\n\t"
        "mov.b64 {a, b}, %1;\n\t"
        "cvt.rn.f16x2.f32 %0, b, a;\n\t"
        "}" : "=r"(d) : "l"(v));
    return d;
}
// unpack f16x2 (u32) -> f32x2 (u64), lanes preserved
__device__ __forceinline__ u64 h2f2(u32 h) {
    u64 r;
    asm("{\n\t"
        ".reg .b16 lo, hi;\n\t"
        ".reg .f32 a, b;\n\t"
        "mov.b32 {lo, hi}, %1;\n\t"
        "cvt.f32.f16 a, lo;\n\t"
        "cvt.f32.f16 b, hi;\n\t"
        "mov.b64 %0, {a, b};\n\t"
        "}" : "=l"(r) : "r"(h));
    return r;
}

// packed adjacent-weight pair for output cols (2c2, 2c2+1): (W[d], W[d-1])
__device__ __forceinline__ u64 wpair(int d) {
    return pack2(gwz(d), gwz(d - 1));
}

// scatter one input position i (0..17) into 4 packed col-pair accumulators
// planes: 0 = s = x+y, 1 = d = x-y, 2 = s^2, 3 = d^2
__device__ __forceinline__ void hacc2(int i, float xa, float yb, u64 acc2[NPL][4]) {
    float sv = xa + yb, dv = xa - yb;
    u64 s2 = dup2(sv), d2 = dup2(dv);
    u64 ss = mul2(s2, s2), dd = mul2(d2, d2);
    #pragma unroll
    for (int c2 = 0; c2 < 4; c2++) {
        int dd_i = i - 2 * c2;
        if (dd_i >= 0 && dd_i <= 11) {
            u64 wp = wpair(dd_i);
            acc2[0][c2] = fma2(s2, wp, acc2[0][c2]);
            acc2[1][c2] = fma2(d2, wp, acc2[1][c2]);
            acc2[2][c2] = fma2(ss, wp, acc2[2][c2]);
            acc2[3][c2] = fma2(dd, wp, acc2[3][c2]);
        }
    }
}

// SSIM from s/d moments: ms=mu_s, md=mu_d, ess=E[ss], edd=E[dd]
__device__ __forceinline__ float ssim_px(float ms, float md, float ess, float edd) {
    float ms2 = ms * ms, md2 = md * md;
    float vs = ess - ms2;            // sx2 + 2sxy + sy2
    float vd = edd - md2;            // sx2 - 2sxy + sy2
    float num = fmaf(0.5f, ms2 - md2, SSIM_C1) * fmaf(0.5f, vs - vd, SSIM_C2);
    float den = fmaf(0.5f, ms2 + md2, SSIM_C1) * fmaf(0.5f, vs + vd, SSIM_C2);
    return __fdividef(num, den);
}

__global__ __launch_bounds__(256, 4) void ssim_main(
    const float* __restrict__ img1,
    const float* __restrict__ img2,
    float* __restrict__ out)
{
    extern __shared__ __align__(16) u32 hb[];   // 4 planes of f16x2 col-pairs
    __shared__ float warpSums[8];
    __shared__ int s_isLast;

    const int tid = threadIdx.x;
    const int bx = blockIdx.x, by = blockIdx.y, bz = blockIdx.z;
    const int row0 = by * TH;
    const int col0 = bx * TW;

    // ========== pass 1: horizontal conv of s,d,ss,dd -> f16x2 hbuf ==========
    // item = halo row r (0..73) x col-group g (0..7, 8 output cols = 4 pairs) -> 592 items
    for (int t = tid; t < HR * 8; t += 256) {
        int r = t >> 3, g = t & 7;
        int gr = row0 - 5 + r;
        u64 acc2[NPL][4];
        #pragma unroll
        for (int q = 0; q < NPL; q++)
            #pragma unroll
            for (int c2 = 0; c2 < 4; c2++) acc2[q][c2] = 0;

        if ((unsigned)gr < 1024u) {
            const float* p1 = img1 + (size_t)bz * 1048576u + (size_t)gr * 1024u;
            const float* p2 = img2 + (size_t)bz * 1048576u + (size_t)gr * 1024u;
            int gb = col0 + 8 * g - 8;   // window: positions i=0..17 at cols gb+3..gb+20
            bool fast = (gb >= 0) && (gb + 24 <= 1024);
            if (fast) {
                #pragma unroll
                for (int m = 0; m < 6; m++) {
                    float4 av = *(const float4*)(p1 + gb + 4 * m);
                    float4 bv = *(const float4*)(p2 + gb + 4 * m);
                    int i0 = 4 * m - 3;
                    if (i0 + 0 >= 0 && i0 + 0 <= 17) hacc2(i0 + 0, av.x, bv.x, acc2);
                    if (i0 + 1 >= 0 && i0 + 1 <= 17) hacc2(i0 + 1, av.y, bv.y, acc2);
                    if (i0 + 2 >= 0 && i0 + 2 <= 17) hacc2(i0 + 2, av.z, bv.z, acc2);
                    if (i0 + 3 >= 0 && i0 + 3 <= 17) hacc2(i0 + 3, av.w, bv.w, acc2);
                }
            } else {
                #pragma unroll
                for (int i = 0; i < 18; i++) {
                    int gc = gb + 3 + i;
                    bool ok = (unsigned)gc < 1024u;
                    float xa = ok ? p1[gc] : 0.f;
                    float yb = ok ? p2[gc] : 0.f;
                    hacc2(i, xa, yb, acc2);
                }
            }
        }
        int sb = r * RS2 + 4 * g;
        #pragma unroll
        for (int q = 0; q < NPL; q++)
            #pragma unroll
            for (int c2 = 0; c2 < 4; c2++)
                hb[q * PS2 + sb + c2] = f2h2(acc2[q][c2]);
    }
    __syncthreads();

    // ========== pass 2: vertical conv (f16x2 -> f32x2 fma, R=4) + SSIM ==========
    // item = col-pair p (0..31) x 4-row chunk c (0..15) -> 512 items, 2 per thread
    float ssum = 0.f;
    for (int it = tid; it < 512; it += 256) {
        int p = it & 31, c = it >> 5;
        u64 A[NPL][4];
        #pragma unroll
        for (int q = 0; q < NPL; q++)
            #pragma unroll
            for (int j = 0; j < 4; j++) A[q][j] = 0;

        const u32* hp = &hb[(4 * c) * RS2 + p];
        #pragma unroll
        for (int k = 0; k < 14; k++) {
            #pragma unroll
            for (int q = 0; q < NPL; q++) {
                u64 v = h2f2(hp[q * PS2 + k * RS2]);
                #pragma unroll
                for (int j = 0; j < 4; j++) {
                    int wi = k - j;
                    if (wi >= 0 && wi <= 10)
                        A[q][j] = fma2(dup2(gw(wi)), v, A[q][j]);
                }
            }
        }
        #pragma unroll
        for (int j = 0; j < 4; j++) {
            float ms0, ms1, md0, md1, es0, es1, ed0, ed1;
            unpack2(A[0][j], ms0, ms1);
            unpack2(A[1][j], md0, md1);
            unpack2(A[2][j], es0, es1);
            unpack2(A[3][j], ed0, ed1);
            ssum += ssim_px(ms0, md0, es0, ed0);
            ssum += ssim_px(ms1, md1, es1, ed1);
        }
    }

    // ========== block reduction (deterministic) ==========
    #pragma unroll
    for (int o = 16; o > 0; o >>= 1)
        ssum += __shfl_down_sync(0xffffffffu, ssum, o);
    const int wid = tid >> 5, lane = tid & 31;
    if (lane == 0) warpSums[wid] = ssum;
    __syncthreads();
    if (tid == 0) {
        float tot = 0.f;
        #pragma unroll
        for (int i = 0; i < 8; i++) tot += warpSums[i];
        int bid = bx + 16 * (by + 16 * bz);
        g_partial[bid] = tot;
        __threadfence();
        int prev = atomicAdd(&g_count, 1);
        s_isLast = (prev == NBLOCKS - 1);
    }
    __syncthreads();

    // ========== last block folds the global mean ==========
    if (s_isLast) {
        __shared__ double dsum[8];
        const float4* p4 = (const float4*)g_partial;   // 1024 float4
        double s = 0.0;
        #pragma unroll
        for (int i = 0; i < 4; i++) {
            float4 v = p4[tid + i * 256];
            s += (double)v.x + (double)v.y + (double)v.z + (double)v.w;
        }
        #pragma unroll
        for (int o = 16; o > 0; o >>= 1)
            s += __shfl_down_sync(0xffffffffu, s, o);
        if (lane == 0) dsum[wid] = s;
        __syncthreads();
        if (tid == 0) {
            double t = 0.0;
            #pragma unroll
            for (int i = 0; i < 8; i++) t += dsum[i];
            out[0] = (float)(t / 16777216.0);
            g_count = 0;   // reset for next graph replay
        }
    }
}

extern "C" void kernel_launch(void* const* d_in, const int* in_sizes, int n_in,
                              void* d_out, int out_size)
{
    const float* img1 = (const float*)d_in[0];
    const float* img2 = (const float*)d_in[1];
    float* out = (float*)d_out;

    cudaFuncSetAttribute(ssim_main, cudaFuncAttributeMaxDynamicSharedMemorySize, HB_BYTES);

    dim3 grid(16, 16, 16);   // 1024/64 x-tiles, 1024/64 y-tiles, 16 batch
    ssim_main<<<grid, 256, HB_BYTES>>>(img1, img2, out);
}

// round 11
// speedup vs baseline: 2.0513x; 1.0053x over previous
#include <cuda_runtime.h>

#define SSIM_C1 1e-4f
#define SSIM_C2 9e-4f

// tile geometry: 64 x 64 outputs per block
#define TW 64
#define TH 64
#define HR 74            // halo rows (TH + 10)
#define RS2 33           // hbuf row stride in half2 units (33 col-pairs)
#define PS2 (HR * RS2)   // plane stride in half2 units
#define NPL 4            // planes: mu_s, mu_d, E[ss], E[dd]
#define HB_BYTES (NPL * PS2 * 4)
#define NBLOCKS (16*16*16)

typedef unsigned long long u64;
typedef unsigned int u32;

__device__ __align__(16) float g_partial[NBLOCKS];
__device__ int g_count = 0;

// 11-tap gaussian (size=11, sigma=1.5), normalized; symmetric
__device__ __forceinline__ float gw(int i) {
    const float W[6] = {0.00102838f, 0.00759876f, 0.03600080f,
                        0.10936070f, 0.21300556f, 0.26601172f};
    return W[(i < 6) ? i : (10 - i)];
}
__device__ __forceinline__ float gwz(int d) {
    return (d >= 0 && d <= 10) ? gw(d) : 0.f;
}

__device__ __forceinline__ u64 pack2(float lo, float hi) {
    u64 r;
    asm("mov.b64 %0, {%1, %2};" : "=l"(r) : "f"(lo), "f"(hi));
    return r;
}
__device__ __forceinline__ u64 dup2(float w) {
    u64 r;
    asm("mov.b64 %0, {%1, %1};" : "=l"(r) : "f"(w));
    return r;
}
__device__ __forceinline__ u64 fma2(u64 a, u64 b, u64 c) {
    u64 d;
    asm("fma.rn.f32x2 %0, %1, %2, %3;" : "=l"(d) : "l"(a), "l"(b), "l"(c));
    return d;
}
__device__ __forceinline__ u64 mul2(u64 a, u64 b) {
    u64 d;
    asm("mul.rn.f32x2 %0, %1, %2;" : "=l"(d) : "l"(a), "l"(b));
    return d;
}
__device__ __forceinline__ void unpack2(u64 v, float& lo, float& hi) {
    asm("mov.b64 {%0, %1}, %2;" : "=f"(lo), "=f"(hi) : "l"(v));
}

// pack f32x2 (u64) -> f16x2 (u32), lanes preserved
__device__ __forceinline__ u32 f2h2(u64 v) {
    u32 d;
    asm("{\n\t"
        ".reg .f32 a, b;\n\t"
        "mov.b64 {a, b}, %1;\n\t"
        "cvt.rn.f16x2.f32 %0, b, a;\n\t"
        "}" : "=r"(d) : "l"(v));
    return d;
}
// unpack f16x2 (u32) -> f32x2 (u64), lanes preserved
__device__ __forceinline__ u64 h2f2(u32 h) {
    u64 r;
    asm("{\n\t"
        ".reg .b16 lo, hi;\n\t"
        ".reg .f32 a, b;\n\t"
        "mov.b32 {lo, hi}, %1;\n\t"
        "cvt.f32.f16 a, lo;\n\t"
        "cvt.f32.f16 b, hi;\n\t"
        "mov.b64 %0, {a, b};\n\t"
        "}" : "=l"(r) : "r"(h));
    return r;
}

// packed adjacent-weight pair for output cols (2c2, 2c2+1): (W[d], W[d-1])
__device__ __forceinline__ u64 wpair(int d) {
    return pack2(gwz(d), gwz(d - 1));
}

// scatter one input position i (0..17) into 4 packed col-pair accumulators
// planes: 0 = s = x+y, 1 = d = x-y, 2 = s^2, 3 = d^2
__device__ __forceinline__ void hacc2(int i, float xa, float yb, u64 acc2[NPL][4]) {
    float sv = xa + yb, dv = xa - yb;
    u64 s2 = dup2(sv), d2 = dup2(dv);
    u64 ss = mul2(s2, s2), dd = mul2(d2, d2);
    #pragma unroll
    for (int c2 = 0; c2 < 4; c2++) {
        int dd_i = i - 2 * c2;
        if (dd_i >= 0 && dd_i <= 11) {
            u64 wp = wpair(dd_i);
            acc2[0][c2] = fma2(s2, wp, acc2[0][c2]);
            acc2[1][c2] = fma2(d2, wp, acc2[1][c2]);
            acc2[2][c2] = fma2(ss, wp, acc2[2][c2]);
            acc2[3][c2] = fma2(dd, wp, acc2[3][c2]);
        }
    }
}

// SSIM from s/d moments: ms=mu_s, md=mu_d, ess=E[ss], edd=E[dd]
__device__ __forceinline__ float ssim_px(float ms, float md, float ess, float edd) {
    float ms2 = ms * ms, md2 = md * md;
    float vs = ess - ms2;            // sx2 + 2sxy + sy2
    float vd = edd - md2;            // sx2 - 2sxy + sy2
    float num = fmaf(0.5f, ms2 - md2, SSIM_C1) * fmaf(0.5f, vs - vd, SSIM_C2);
    float den = fmaf(0.5f, ms2 + md2, SSIM_C1) * fmaf(0.5f, vs + vd, SSIM_C2);
    return __fdividef(num, den);
}

__global__ __launch_bounds__(256, 4) void ssim_main(
    const float* __restrict__ img1,
    const float* __restrict__ img2,
    float* __restrict__ out)
{
    extern __shared__ __align__(16) u32 hb[];   // 4 planes of f16x2 col-pairs
    __shared__ float warpSums[8];
    __shared__ int s_isLast;

    const int tid = threadIdx.x;
    const int bx = blockIdx.x, by = blockIdx.y, bz = blockIdx.z;
    const int row0 = by * TH;
    const int col0 = bx * TW;

    // ========== pass 1: horizontal conv of s,d,ss,dd -> f16x2 hbuf ==========
    // item = halo row r (0..73) x col-group g (0..7, 8 output cols = 4 pairs) -> 592 items
    for (int t = tid; t < HR * 8; t += 256) {
        int r = t >> 3, g = t & 7;
        int gr = row0 - 5 + r;
        u64 acc2[NPL][4];
        #pragma unroll
        for (int q = 0; q < NPL; q++)
            #pragma unroll
            for (int c2 = 0; c2 < 4; c2++) acc2[q][c2] = 0;

        if ((unsigned)gr < 1024u) {
            const float* p1 = img1 + (size_t)bz * 1048576u + (size_t)gr * 1024u;
            const float* p2 = img2 + (size_t)bz * 1048576u + (size_t)gr * 1024u;
            int gb = col0 + 8 * g - 8;   // window: positions i=0..17 at cols gb+3..gb+20
            bool fast = (gb >= 0) && (gb + 24 <= 1024);
            if (fast) {
                #pragma unroll
                for (int m = 0; m < 6; m++) {
                    float4 av = *(const float4*)(p1 + gb + 4 * m);
                    float4 bv = *(const float4*)(p2 + gb + 4 * m);
                    int i0 = 4 * m - 3;
                    if (i0 + 0 >= 0 && i0 + 0 <= 17) hacc2(i0 + 0, av.x, bv.x, acc2);
                    if (i0 + 1 >= 0 && i0 + 1 <= 17) hacc2(i0 + 1, av.y, bv.y, acc2);
                    if (i0 + 2 >= 0 && i0 + 2 <= 17) hacc2(i0 + 2, av.z, bv.z, acc2);
                    if (i0 + 3 >= 0 && i0 + 3 <= 17) hacc2(i0 + 3, av.w, bv.w, acc2);
                }
            } else {
                #pragma unroll
                for (int i = 0; i < 18; i++) {
                    int gc = gb + 3 + i;
                    bool ok = (unsigned)gc < 1024u;
                    float xa = ok ? p1[gc] : 0.f;
                    float yb = ok ? p2[gc] : 0.f;
                    hacc2(i, xa, yb, acc2);
                }
            }
        }
        int sb = r * RS2 + 4 * g;
        #pragma unroll
        for (int q = 0; q < NPL; q++)
            #pragma unroll
            for (int c2 = 0; c2 < 4; c2++)
                hb[q * PS2 + sb + c2] = f2h2(acc2[q][c2]);
    }
    __syncthreads();

    // ========== pass 2: vertical conv (f16x2 -> f32x2 fma, R=4) + SSIM ==========
    // item = col-pair p (0..31) x 4-row chunk c (0..15) -> 512 items, 2 per thread
    float ssum = 0.f;
    for (int it = tid; it < 512; it += 256) {
        int p = it & 31, c = it >> 5;
        u64 A[NPL][4];
        #pragma unroll
        for (int q = 0; q < NPL; q++)
            #pragma unroll
            for (int j = 0; j < 4; j++) A[q][j] = 0;

        const u32* hp = &hb[(4 * c) * RS2 + p];
        #pragma unroll
        for (int k = 0; k < 14; k++) {
            #pragma unroll
            for (int q = 0; q < NPL; q++) {
                u64 v = h2f2(hp[q * PS2 + k * RS2]);
                #pragma unroll
                for (int j = 0; j < 4; j++) {
                    int wi = k - j;
                    if (wi >= 0 && wi <= 10)
                        A[q][j] = fma2(dup2(gw(wi)), v, A[q][j]);
                }
            }
        }
        #pragma unroll
        for (int j = 0; j < 4; j++) {
            float ms0, ms1, md0, md1, es0, es1, ed0, ed1;
            unpack2(A[0][j], ms0, ms1);
            unpack2(A[1][j], md0, md1);
            unpack2(A[2][j], es0, es1);
            unpack2(A[3][j], ed0, ed1);
            ssum += ssim_px(ms0, md0, es0, ed0);
            ssum += ssim_px(ms1, md1, es1, ed1);
        }
    }

    // ========== block reduction (deterministic) ==========
    #pragma unroll
    for (int o = 16; o > 0; o >>= 1)
        ssum += __shfl_down_sync(0xffffffffu, ssum, o);
    const int wid = tid >> 5, lane = tid & 31;
    if (lane == 0) warpSums[wid] = ssum;
    __syncthreads();
    if (tid == 0) {
        float tot = 0.f;
        #pragma unroll
        for (int i = 0; i < 8; i++) tot += warpSums[i];
        int bid = bx + 16 * (by + 16 * bz);
        g_partial[bid] = tot;
        __threadfence();
        int prev = atomicAdd(&g_count, 1);
        s_isLast = (prev == NBLOCKS - 1);
    }
    __syncthreads();

    // ========== last block folds the global mean ==========
    if (s_isLast) {
        __shared__ double dsum[8];
        const float4* p4 = (const float4*)g_partial;   // 1024 float4
        double s = 0.0;
        #pragma unroll
        for (int i = 0; i < 4; i++) {
            float4 v = p4[tid + i * 256];
            s += (double)v.x + (double)v.y + (double)v.z + (double)v.w;
        }
        #pragma unroll
        for (int o = 16; o > 0; o >>= 1)
            s += __shfl_down_sync(0xffffffffu, s, o);
        if (lane == 0) dsum[wid] = s;
        __syncthreads();
        if (tid == 0) {
            double t = 0.0;
            #pragma unroll
            for (int i = 0; i < 8; i++) t += dsum[i];
            out[0] = (float)(t / 16777216.0);
            g_count = 0;   // reset for next graph replay
        }
    }
}

extern "C" void kernel_launch(void* const* d_in, const int* in_sizes, int n_in,
                              void* d_out, int out_size)
{
    const float* img1 = (const float*)d_in[0];
    const float* img2 = (const float*)d_in[1];
    float* out = (float*)d_out;

    cudaFuncSetAttribute(ssim_main, cudaFuncAttributeMaxDynamicSharedMemorySize, HB_BYTES);

    dim3 grid(16, 16, 16);   // 1024/64 x-tiles, 1024/64 y-tiles, 16 batch
    ssim_main<<<grid, 256, HB_BYTES>>>(img1, img2, out);
}

// round 12
// speedup vs baseline: 2.0589x; 1.0037x over previous
#include <cuda_runtime.h>

#define SSIM_C1 1e-4f
#define SSIM_C2 9e-4f

// tile geometry: 64 x 64 outputs per block
#define TW 64
#define TH 64
#define HR 74            // halo rows (TH + 10)
#define RS2 33           // hbuf row stride in u64 units (33 col-pairs)
#define PS2 (HR * RS2)   // plane-group stride in u64 units
#define HB_BYTES (2 * PS2 * 8)   // 2 groups x PS2 u64
#define NBLOCKS (16*16*16)

typedef unsigned long long u64;
typedef unsigned int u32;

__device__ __align__(16) float g_partial[NBLOCKS];
__device__ int g_count = 0;

// 11-tap gaussian (size=11, sigma=1.5), normalized; symmetric
__device__ __forceinline__ float gw(int i) {
    const float W[6] = {0.00102838f, 0.00759876f, 0.03600080f,
                        0.10936070f, 0.21300556f, 0.26601172f};
    return W[(i < 6) ? i : (10 - i)];
}
__device__ __forceinline__ float gwz(int d) {
    return (d >= 0 && d <= 10) ? gw(d) : 0.f;
}

__device__ __forceinline__ u64 pack2(float lo, float hi) {
    u64 r;
    asm("mov.b64 %0, {%1, %2};" : "=l"(r) : "f"(lo), "f"(hi));
    return r;
}
__device__ __forceinline__ u64 dup2(float w) {
    u64 r;
    asm("mov.b64 %0, {%1, %1};" : "=l"(r) : "f"(w));
    return r;
}
__device__ __forceinline__ u64 fma2(u64 a, u64 b, u64 c) {
    u64 d;
    asm("fma.rn.f32x2 %0, %1, %2, %3;" : "=l"(d) : "l"(a), "l"(b), "l"(c));
    return d;
}
__device__ __forceinline__ u64 mul2(u64 a, u64 b) {
    u64 d;
    asm("mul.rn.f32x2 %0, %1, %2;" : "=l"(d) : "l"(a), "l"(b));
    return d;
}
__device__ __forceinline__ void unpack2(u64 v, float& lo, float& hi) {
    asm("mov.b64 {%0, %1}, %2;" : "=f"(lo), "=f"(hi) : "l"(v));
}

// pack f32x2 (u64) -> f16x2 (u32), lanes preserved
__device__ __forceinline__ u32 f2h2(u64 v) {
    u32 d;
    asm("{\n\t"
        ".reg .f32 a, b;\n\t"
        "mov.b64 {a, b}, %1;\n\t"
        "cvt.rn.f16x2.f32 %0, b, a;\n\t"
        "}" : "=r"(d) : "l"(v));
    return d;
}
// unpack f16x2 (u32) -> f32x2 (u64), lanes preserved
__device__ __forceinline__ u64 h2f2(u32 h) {
    u64 r;
    asm("{\n\t"
        ".reg .b16 lo, hi;\n\t"
        ".reg .f32 a, b;\n\t"
        "mov.b32 {lo, hi}, %1;\n\t"
        "cvt.f32.f16 a, lo;\n\t"
        "cvt.f32.f16 b, hi;\n\t"
        "mov.b64 %0, {a, b};\n\t"
        "}" : "=l"(r) : "r"(h));
    return r;
}
__device__ __forceinline__ u64 cat32(u32 lo, u32 hi) {
    u64 r;
    asm("mov.b64 %0, {%1, %2};" : "=l"(r) : "r"(lo), "r"(hi));
    return r;
}
__device__ __forceinline__ void split64(u64 v, u32& lo, u32& hi) {
    asm("mov.b64 {%0, %1}, %2;" : "=r"(lo), "=r"(hi) : "l"(v));
}

// packed adjacent-weight pair for output cols (2c2, 2c2+1): (W[d], W[d-1])
__device__ __forceinline__ u64 wpair(int d) {
    return pack2(gwz(d), gwz(d - 1));
}

// scatter one input position i (0..17) into 4 packed col-pair accumulators
// planes: 0 = s = x+y, 1 = d = x-y, 2 = s^2, 3 = d^2
__device__ __forceinline__ void hacc2(int i, float xa, float yb, u64 acc2[4][4]) {
    float sv = xa + yb, dv = xa - yb;
    u64 s2 = dup2(sv), d2 = dup2(dv);
    u64 ss = mul2(s2, s2), dd = mul2(d2, d2);
    #pragma unroll
    for (int c2 = 0; c2 < 4; c2++) {
        int di = i - 2 * c2;
        if (di >= 0 && di <= 11) {
            u64 wp = wpair(di);
            acc2[0][c2] = fma2(s2, wp, acc2[0][c2]);
            acc2[1][c2] = fma2(d2, wp, acc2[1][c2]);
            acc2[2][c2] = fma2(ss, wp, acc2[2][c2]);
            acc2[3][c2] = fma2(dd, wp, acc2[3][c2]);
        }
    }
}

__global__ __launch_bounds__(256, 4) void ssim_main(
    const float* __restrict__ img1,
    const float* __restrict__ img2,
    float* __restrict__ out)
{
    extern __shared__ __align__(16) u64 hb[];   // 2 groups: [s|d] and [ss|dd] f16x2 pairs
    __shared__ float warpSums[8];
    __shared__ int s_isLast;

    const int tid = threadIdx.x;
    const int bx = blockIdx.x, by = blockIdx.y, bz = blockIdx.z;
    const int row0 = by * TH;
    const int col0 = bx * TW;

    // ========== pass 1: horizontal conv of s,d,ss,dd -> interleaved f16x2 hbuf ==========
    // item = halo row r (0..73) x col-group g (0..7, 8 output cols = 4 pairs) -> 592 items
    for (int t = tid; t < HR * 8; t += 256) {
        int r = t >> 3, g = t & 7;
        int gr = row0 - 5 + r;
        u64 acc2[4][4];
        #pragma unroll
        for (int q = 0; q < 4; q++)
            #pragma unroll
            for (int c2 = 0; c2 < 4; c2++) acc2[q][c2] = 0;

        if ((unsigned)gr < 1024u) {
            const float* p1 = img1 + (size_t)bz * 1048576u + (size_t)gr * 1024u;
            const float* p2 = img2 + (size_t)bz * 1048576u + (size_t)gr * 1024u;
            int gb = col0 + 8 * g - 8;   // window: positions i=0..17 at cols gb+3..gb+20
            bool fast = (gb >= 0) && (gb + 24 <= 1024);
            if (fast) {
                #pragma unroll
                for (int m = 0; m < 6; m++) {
                    float4 av = *(const float4*)(p1 + gb + 4 * m);
                    float4 bv = *(const float4*)(p2 + gb + 4 * m);
                    int i0 = 4 * m - 3;
                    if (i0 + 0 >= 0 && i0 + 0 <= 17) hacc2(i0 + 0, av.x, bv.x, acc2);
                    if (i0 + 1 >= 0 && i0 + 1 <= 17) hacc2(i0 + 1, av.y, bv.y, acc2);
                    if (i0 + 2 >= 0 && i0 + 2 <= 17) hacc2(i0 + 2, av.z, bv.z, acc2);
                    if (i0 + 3 >= 0 && i0 + 3 <= 17) hacc2(i0 + 3, av.w, bv.w, acc2);
                }
            } else {
                #pragma unroll
                for (int i = 0; i < 18; i++) {
                    int gc = gb + 3 + i;
                    bool ok = (unsigned)gc < 1024u;
                    float xa = ok ? p1[gc] : 0.f;
                    float yb = ok ? p2[gc] : 0.f;
                    hacc2(i, xa, yb, acc2);
                }
            }
        }
        int sb = r * RS2 + 4 * g;
        #pragma unroll
        for (int c2 = 0; c2 < 4; c2++) {
            hb[sb + c2]       = cat32(f2h2(acc2[0][c2]), f2h2(acc2[1][c2]));   // (s, d)
            hb[PS2 + sb + c2] = cat32(f2h2(acc2[2][c2]), f2h2(acc2[3][c2]));   // (ss, dd)
        }
    }
    __syncthreads();

    // ========== pass 2: vertical conv (LDS.64 -> 2x h2f2 -> f32x2 fma, R=4) + SSIM ==========
    // item = col-pair p (0..31) x 4-row chunk c (0..15) -> 512 items, 2 per thread
    const u64 half2c  = dup2(0.5f);
    const u64 mhalf2c = dup2(-0.5f);
    const u64 c1p = dup2(SSIM_C1);
    const u64 c2p = dup2(SSIM_C2);
    const u64 m1p = dup2(-1.f);

    float ssum = 0.f;
    for (int it = tid; it < 512; it += 256) {
        int p = it & 31, c = it >> 5;
        u64 A[4][4];
        #pragma unroll
        for (int q = 0; q < 4; q++)
            #pragma unroll
            for (int j = 0; j < 4; j++) A[q][j] = 0;

        const u64* hp = &hb[(4 * c) * RS2 + p];
        #pragma unroll
        for (int k = 0; k < 14; k++) {
            u64 vA = hp[k * RS2];          // (s, d) half2 pair
            u64 vB = hp[PS2 + k * RS2];    // (ss, dd) half2 pair
            u32 sh, dh, ssh, ddh;
            split64(vA, sh, dh);
            split64(vB, ssh, ddh);
            u64 vs_ = h2f2(sh), vd_ = h2f2(dh), vss = h2f2(ssh), vdd = h2f2(ddh);
            #pragma unroll
            for (int j = 0; j < 4; j++) {
                int wi = k - j;
                if (wi >= 0 && wi <= 10) {
                    u64 w = dup2(gw(wi));
                    A[0][j] = fma2(w, vs_, A[0][j]);
                    A[1][j] = fma2(w, vd_, A[1][j]);
                    A[2][j] = fma2(w, vss, A[2][j]);
                    A[3][j] = fma2(w, vdd, A[3][j]);
                }
            }
        }
        #pragma unroll
        for (int j = 0; j < 4; j++) {
            u64 ms = A[0][j], md = A[1][j], ess = A[2][j], edd = A[3][j];
            u64 ms2 = mul2(ms, ms);
            u64 md2 = mul2(md, md);
            u64 vs = fma2(ms2, m1p, ess);                       // ess - ms2
            u64 vd = fma2(md2, m1p, edd);                       // edd - md2
            u64 numA = fma2(ms2, half2c, fma2(md2, mhalf2c, c1p));
            u64 denA = fma2(ms2, half2c, fma2(md2, half2c,  c1p));
            u64 numB = fma2(vs,  half2c, fma2(vd,  mhalf2c, c2p));
            u64 denB = fma2(vs,  half2c, fma2(vd,  half2c,  c2p));
            u64 num = mul2(numA, numB);
            u64 den = mul2(denA, denB);
            float n0, n1, d0, d1;
            unpack2(num, n0, n1);
            unpack2(den, d0, d1);
            ssum += __fdividef(n0, d0);
            ssum += __fdividef(n1, d1);
        }
    }

    // ========== block reduction (deterministic) ==========
    #pragma unroll
    for (int o = 16; o > 0; o >>= 1)
        ssum += __shfl_down_sync(0xffffffffu, ssum, o);
    const int wid = tid >> 5, lane = tid & 31;
    if (lane == 0) warpSums[wid] = ssum;
    __syncthreads();
    if (tid == 0) {
        float tot = 0.f;
        #pragma unroll
        for (int i = 0; i < 8; i++) tot += warpSums[i];
        int bid = bx + 16 * (by + 16 * bz);
        g_partial[bid] = tot;
        __threadfence();
        int prev = atomicAdd(&g_count, 1);
        s_isLast = (prev == NBLOCKS - 1);
    }
    __syncthreads();

    // ========== last block folds the global mean ==========
    if (s_isLast) {
        __shared__ double dsum[8];
        const float4* p4 = (const float4*)g_partial;   // 1024 float4
        double s = 0.0;
        #pragma unroll
        for (int i = 0; i < 4; i++) {
            float4 v = p4[tid + i * 256];
            s += (double)v.x + (double)v.y + (double)v.z + (double)v.w;
        }
        #pragma unroll
        for (int o = 16; o > 0; o >>= 1)
            s += __shfl_down_sync(0xffffffffu, s, o);
        if (lane == 0) dsum[wid] = s;
        __syncthreads();
        if (tid == 0) {
            double t = 0.0;
            #pragma unroll
            for (int i = 0; i < 8; i++) t += dsum[i];
            out[0] = (float)(t / 16777216.0);
            g_count = 0;   // reset for next graph replay
        }
    }
}

extern "C" void kernel_launch(void* const* d_in, const int* in_sizes, int n_in,
                              void* d_out, int out_size)
{
    const float* img1 = (const float*)d_in[0];
    const float* img2 = (const float*)d_in[1];
    float* out = (float*)d_out;

    cudaFuncSetAttribute(ssim_main, cudaFuncAttributeMaxDynamicSharedMemorySize, HB_BYTES);

    dim3 grid(16, 16, 16);   // 1024/64 x-tiles, 1024/64 y-tiles, 16 batch
    ssim_main<<<grid, 256, HB_BYTES>>>(img1, img2, out);
}